// round 6
// baseline (speedup 1.0000x reference)
#include <cuda_runtime.h>
#include <cuda_bf16.h>

// SphereTracingRenderer: fused 64-iter sphere trace + 3->128->3 MLP, masked.
// R2 body (best known) + CTA-level tile work stealing:
//   grid = 740 = 148 SMs x 5 resident CTAs (launch_bounds(256,5));
//   each CTA claims 256-quad tiles via one global atomic -> no wave
//   quantization (1024 tiles over 740 slots was ~2 waves before).
// 4 rays/thread as two f32x2 packed pairs (HW FFMA2 via PTX).
// Weights pre-duplicated in shared (7 LDS.128 per 2 hidden units).
// Warp-coherent early exit in the trace using SDF monotonicity.

#define N_BLKS 16           // 16 blocks x 4 iters = 64
#define HIDDEN 128
#define SDF_EPS 1e-4f
#define EPS_HIT 5e-5f       // s < this => final s63 < SDF_EPS (monotone decrease)
#define EPS_MISS 2e-4f      // s increasing and > this => final s63 > SDF_EPS
#define GRID_CTAS 740       // 148 SMs x 5 CTAs
#define TILE 256            // quads per tile = blockDim

typedef unsigned long long u64;

__device__ unsigned int g_counter;

__device__ __forceinline__ u64 pk(float a, float b) {
    u64 r; asm("mov.b64 %0,{%1,%2};" : "=l"(r) : "f"(a), "f"(b)); return r;
}
__device__ __forceinline__ void upk(u64 v, float& a, float& b) {
    asm("mov.b64 {%0,%1},%2;" : "=f"(a), "=f"(b) : "l"(v));
}
__device__ __forceinline__ u64 fma2(u64 a, u64 b, u64 c) {
    u64 d; asm("fma.rn.f32x2 %0,%1,%2,%3;" : "=l"(d) : "l"(a), "l"(b), "l"(c)); return d;
}
__device__ __forceinline__ u64 mul2(u64 a, u64 b) {
    u64 d; asm("mul.rn.f32x2 %0,%1,%2;" : "=l"(d) : "l"(a), "l"(b)); return d;
}
__device__ __forceinline__ u64 add2(u64 a, u64 b) {
    u64 d; asm("add.rn.f32x2 %0,%1,%2;" : "=l"(d) : "l"(a), "l"(b)); return d;
}
__device__ __forceinline__ float sqap(float x) {
    float r; asm("sqrt.approx.f32 %0,%1;" : "=f"(r) : "f"(x)); return r;
}
__device__ __forceinline__ float rcpa(float x) {
    float r; asm("rcp.approx.f32 %0,%1;" : "=f"(r) : "f"(x)); return r;
}
__device__ __forceinline__ float sgm(float x) {
    return rcpa(1.0f + __expf(-x));
}
__device__ __forceinline__ u64 relu2(u64 h) {
    float h0, h1; upk(h, h0, h1);
    return pk(fmaxf(h0, 0.f), fmaxf(h1, 0.f));
}

__global__ void reset_counter_kernel() { g_counter = 0; }

__global__ void __launch_bounds__(256, 5)
sphere_trace_kernel(const float* __restrict__ origins,
                    const float* __restrict__ directions,
                    const float* __restrict__ center,
                    const float* __restrict__ radius,
                    const float* __restrict__ W1,
                    const float* __restrict__ b1,
                    const float* __restrict__ W2,
                    const float* __restrict__ b2,
                    float* __restrict__ out,
                    int n_quads, int n_tiles)
{
    // Duplicated layout per hidden unit j:
    //   sW1[2j]   = {w1x,w1x, w1y,w1y}   sW1[2j+1] = {w1z,w1z, b1,b1}
    //   sW2[j]    = {w20,w20, w21,w21}
    //   sW22 u64 stream: elem j = {w22_j, w22_j}; read as ulonglong2 per pair
    __shared__ ulonglong2 sW1[2 * HIDDEN];
    __shared__ ulonglong2 sW2[HIDDEN];
    __shared__ ulonglong2 sW22[HIDDEN / 2];
    __shared__ int s_tile;

    int t = threadIdx.x;
    if (t < HIDDEN) {
        float w1x = W1[t], w1y = W1[HIDDEN + t], w1z = W1[2 * HIDDEN + t], bb = b1[t];
        float* p = (float*)&sW1[2 * t];
        p[0] = w1x; p[1] = w1x; p[2] = w1y; p[3] = w1y;
        p[4] = w1z; p[5] = w1z; p[6] = bb;  p[7] = bb;
        float u = W2[3 * t], v = W2[3 * t + 1], w = W2[3 * t + 2];
        float* q = (float*)&sW2[t];
        q[0] = u; q[1] = u; q[2] = v; q[3] = v;
        ((u64*)sW22)[t] = pk(w, w);
    }

    float cx = center[0], cy = center[1], cz = center[2];
    float rad = radius[0];

    const float4* og = (const float4*)origins;
    const float4* dg = (const float4*)directions;
    float4* o4 = (float4*)out;

    for (;;) {
        __syncthreads();                 // protect s_tile; also covers smem init
        if (t == 0) s_tile = (int)atomicAdd(&g_counter, 1u);
        __syncthreads();
        int tile = s_tile;
        if (tile >= n_tiles) break;
        int i = tile * TILE + t;         // quad index: rays 4i .. 4i+3
        if (i >= n_quads) continue;

        // Load 4 rays (12 floats) as 3 float4, fully coalesced.
        float4 A = og[3 * i], B = og[3 * i + 1], C = og[3 * i + 2];
        float4 DA = dg[3 * i], DB = dg[3 * i + 1], DC = dg[3 * i + 2];
        // ray0=(A.x,A.y,A.z) ray1=(A.w,B.x,B.y) ray2=(B.z,B.w,C.x) ray3=(C.y,C.z,C.w)

        // Pair P = rays {0,1}, pair Q = rays {2,3}; centered coords q = p - c.
        u64 qxP = pk(A.x - cx, A.w - cx);
        u64 qyP = pk(A.y - cy, B.x - cy);
        u64 qzP = pk(A.z - cz, B.y - cz);
        u64 qxQ = pk(B.z - cx, C.y - cx);
        u64 qyQ = pk(B.w - cy, C.z - cy);
        u64 qzQ = pk(C.x - cz, C.w - cz);
        u64 vxP = pk(DA.x, DA.w), vyP = pk(DA.y, DB.x), vzP = pk(DA.z, DB.y);
        u64 vxQ = pk(DB.z, DC.y), vyQ = pk(DB.w, DC.z), vzQ = pk(DC.x, DC.w);

        float sP0 = 0.f, sP1 = 0.f, sQ0 = 0.f, sQ1 = 0.f;
        float pP0 = 1e30f, pP1 = 1e30f, pQ0 = 1e30f, pQ1 = 1e30f;

        #pragma unroll 1
        for (int blk = 0; blk < N_BLKS; ++blk) {
            #pragma unroll
            for (int u = 0; u < 4; ++u) {
                u64 nP = fma2(qxP, qxP, fma2(qyP, qyP, mul2(qzP, qzP)));
                u64 nQ = fma2(qxQ, qxQ, fma2(qyQ, qyQ, mul2(qzQ, qzQ)));
                float n0, n1; upk(nP, n0, n1);
                sP0 = sqap(n0) - rad;
                sP1 = sqap(n1) - rad;
                float n2, n3; upk(nQ, n2, n3);
                sQ0 = sqap(n2) - rad;
                sQ1 = sqap(n3) - rad;
                u64 s2P = pk(sP0, sP1);
                u64 s2Q = pk(sQ0, sQ1);
                qxP = fma2(s2P, vxP, qxP);
                qyP = fma2(s2P, vyP, qyP);
                qzP = fma2(s2P, vzP, qzP);
                qxQ = fma2(s2Q, vxQ, qxQ);
                qyQ = fma2(s2Q, vyQ, qyQ);
                qzQ = fma2(s2Q, vzQ, qzQ);
            }
            // Done = converged hit (mask guaranteed 1) or past-perigee miss
            // (mask guaranteed 0). Exit when all 4 rays of this thread done.
            bool d0 = (sP0 < EPS_HIT) | ((sP0 > pP0) & (sP0 > EPS_MISS));
            bool d1 = (sP1 < EPS_HIT) | ((sP1 > pP1) & (sP1 > EPS_MISS));
            bool d2 = (sQ0 < EPS_HIT) | ((sQ0 > pQ0) & (sQ0 > EPS_MISS));
            bool d3 = (sQ1 < EPS_HIT) | ((sQ1 > pQ1) & (sQ1 > EPS_MISS));
            if (d0 & d1 & d2 & d3) break;
            pP0 = sP0; pP1 = sP1; pQ0 = sQ0; pQ1 = sQ1;
        }
        bool m0 = sP0 < SDF_EPS;
        bool m1 = sP1 < SDF_EPS;
        bool m2 = sQ0 < SDF_EPS;
        bool m3 = sQ1 < SDF_EPS;

        // points = q + center
        u64 cX = pk(cx, cx), cY = pk(cy, cy), cZ = pk(cz, cz);
        u64 pxP = add2(qxP, cX), pyP = add2(qyP, cY), pzP = add2(qzP, cZ);
        u64 pxQ = add2(qxQ, cX), pyQ = add2(qyQ, cY), pzQ = add2(qzQ, cZ);

        float bo0 = b2[0], bo1 = b2[1], bo2 = b2[2];
        u64 a0P = pk(bo0, bo0), a1P = pk(bo1, bo1), a2P = pk(bo2, bo2);
        u64 a0Q = a0P, a1Q = a1P, a2Q = a2P;

        #pragma unroll 4
        for (int p = 0; p < HIDDEN / 2; ++p) {
            // hidden units j = 2p (even) and 2p+1 (odd): 7 LDS.128 total
            ulonglong2 wA0 = sW1[4 * p + 0];
            ulonglong2 wB0 = sW1[4 * p + 1];
            ulonglong2 wA1 = sW1[4 * p + 2];
            ulonglong2 wB1 = sW1[4 * p + 3];
            ulonglong2 uA0 = sW2[2 * p + 0];
            ulonglong2 uA1 = sW2[2 * p + 1];
            ulonglong2 w22 = sW22[p];          // .x = j even, .y = j odd

            u64 hP = fma2(pxP, wA0.x, fma2(pyP, wA0.y, fma2(pzP, wB0.x, wB0.y)));
            u64 hQ = fma2(pxQ, wA0.x, fma2(pyQ, wA0.y, fma2(pzQ, wB0.x, wB0.y)));
            hP = relu2(hP); hQ = relu2(hQ);
            a0P = fma2(hP, uA0.x, a0P);
            a1P = fma2(hP, uA0.y, a1P);
            a2P = fma2(hP, w22.x, a2P);
            a0Q = fma2(hQ, uA0.x, a0Q);
            a1Q = fma2(hQ, uA0.y, a1Q);
            a2Q = fma2(hQ, w22.x, a2Q);

            u64 gP = fma2(pxP, wA1.x, fma2(pyP, wA1.y, fma2(pzP, wB1.x, wB1.y)));
            u64 gQ = fma2(pxQ, wA1.x, fma2(pyQ, wA1.y, fma2(pzQ, wB1.x, wB1.y)));
            gP = relu2(gP); gQ = relu2(gQ);
            a0P = fma2(gP, uA1.x, a0P);
            a1P = fma2(gP, uA1.y, a1P);
            a2P = fma2(gP, w22.y, a2P);
            a0Q = fma2(gQ, uA1.x, a0Q);
            a1Q = fma2(gQ, uA1.y, a1Q);
            a2Q = fma2(gQ, w22.y, a2Q);
        }

        float x00, x10, x01, x11, x02, x12;     // rays 0,1
        upk(a0P, x00, x10); upk(a1P, x01, x11); upk(a2P, x02, x12);
        float x20, x30, x21, x31, x22, x32;     // rays 2,3
        upk(a0Q, x20, x30); upk(a1Q, x21, x31); upk(a2Q, x22, x32);

        float r0c0 = m0 ? sgm(x00) : 0.f, r0c1 = m0 ? sgm(x01) : 0.f, r0c2 = m0 ? sgm(x02) : 0.f;
        float r1c0 = m1 ? sgm(x10) : 0.f, r1c1 = m1 ? sgm(x11) : 0.f, r1c2 = m1 ? sgm(x12) : 0.f;
        float r2c0 = m2 ? sgm(x20) : 0.f, r2c1 = m2 ? sgm(x21) : 0.f, r2c2 = m2 ? sgm(x22) : 0.f;
        float r3c0 = m3 ? sgm(x30) : 0.f, r3c1 = m3 ? sgm(x31) : 0.f, r3c2 = m3 ? sgm(x32) : 0.f;

        o4[3 * i]     = make_float4(r0c0, r0c1, r0c2, r1c0);
        o4[3 * i + 1] = make_float4(r1c1, r1c2, r2c0, r2c1);
        o4[3 * i + 2] = make_float4(r2c2, r3c0, r3c1, r3c2);
    }
}

extern "C" void kernel_launch(void* const* d_in, const int* in_sizes, int n_in,
                              void* d_out, int out_size) {
    const float* origins    = (const float*)d_in[0];
    const float* directions = (const float*)d_in[1];
    const float* center     = (const float*)d_in[2];
    const float* radius     = (const float*)d_in[3];
    const float* W1         = (const float*)d_in[4];
    const float* b1         = (const float*)d_in[5];
    const float* W2         = (const float*)d_in[6];
    const float* b2         = (const float*)d_in[7];
    float* out = (float*)d_out;

    int n_rays = in_sizes[0] / 3;
    int n_quads = n_rays / 4;
    int n_tiles = (n_quads + TILE - 1) / TILE;

    reset_counter_kernel<<<1, 1>>>();
    sphere_trace_kernel<<<GRID_CTAS, 256>>>(origins, directions, center, radius,
                                            W1, b1, W2, b2, out, n_quads, n_tiles);
}

// round 7
// speedup vs baseline: 1.0718x; 1.0718x over previous
#include <cuda_runtime.h>
#include <cuda_bf16.h>

// SphereTracingRenderer: fused 64-iter sphere trace + 3->128->3 MLP, masked.
// R2 structure (plain grid, no stealing) scaled to 8 rays/thread as four
// f32x2 packed pairs (HW FFMA2 via PTX). Each broadcast weight LDS.128 now
// serves 8 rays; per-ray loop overhead halves vs the 4-ray version.
// Warp-coherent early exit in the trace using SDF monotonicity.

#define N_BLKS 16           // 16 blocks x 4 iters = 64
#define HIDDEN 128
#define SDF_EPS 1e-4f
#define EPS_HIT 5e-5f       // s < this => final s63 < SDF_EPS (monotone decrease)
#define EPS_MISS 2e-4f      // s increasing and > this => final s63 > SDF_EPS
#define NPAIR 4             // 4 f32x2 pairs = 8 rays per thread

typedef unsigned long long u64;

__device__ __forceinline__ u64 pk(float a, float b) {
    u64 r; asm("mov.b64 %0,{%1,%2};" : "=l"(r) : "f"(a), "f"(b)); return r;
}
__device__ __forceinline__ void upk(u64 v, float& a, float& b) {
    asm("mov.b64 {%0,%1},%2;" : "=f"(a), "=f"(b) : "l"(v));
}
__device__ __forceinline__ u64 fma2(u64 a, u64 b, u64 c) {
    u64 d; asm("fma.rn.f32x2 %0,%1,%2,%3;" : "=l"(d) : "l"(a), "l"(b), "l"(c)); return d;
}
__device__ __forceinline__ u64 mul2(u64 a, u64 b) {
    u64 d; asm("mul.rn.f32x2 %0,%1,%2;" : "=l"(d) : "l"(a), "l"(b)); return d;
}
__device__ __forceinline__ u64 add2(u64 a, u64 b) {
    u64 d; asm("add.rn.f32x2 %0,%1,%2;" : "=l"(d) : "l"(a), "l"(b)); return d;
}
__device__ __forceinline__ float sqap(float x) {
    float r; asm("sqrt.approx.f32 %0,%1;" : "=f"(r) : "f"(x)); return r;
}
__device__ __forceinline__ float rcpa(float x) {
    float r; asm("rcp.approx.f32 %0,%1;" : "=f"(r) : "f"(x)); return r;
}
__device__ __forceinline__ float sgm(float x) {
    return rcpa(1.0f + __expf(-x));
}
__device__ __forceinline__ u64 relu2(u64 h) {
    float h0, h1; upk(h, h0, h1);
    return pk(fmaxf(h0, 0.f), fmaxf(h1, 0.f));
}

__global__ void __launch_bounds__(256, 3)
sphere_trace_kernel(const float* __restrict__ origins,
                    const float* __restrict__ directions,
                    const float* __restrict__ center,
                    const float* __restrict__ radius,
                    const float* __restrict__ W1,
                    const float* __restrict__ b1,
                    const float* __restrict__ W2,
                    const float* __restrict__ b2,
                    float* __restrict__ out,
                    int n_oct)
{
    // Duplicated layout per hidden unit j:
    //   sW1[2j]   = {w1x,w1x, w1y,w1y}   sW1[2j+1] = {w1z,w1z, b1,b1}
    //   sW2[j]    = {w20,w20, w21,w21}
    //   sW22 u64 stream: elem j = {w22_j, w22_j}; read as ulonglong2 per pair
    __shared__ ulonglong2 sW1[2 * HIDDEN];
    __shared__ ulonglong2 sW2[HIDDEN];
    __shared__ ulonglong2 sW22[HIDDEN / 2];

    int t = threadIdx.x;
    if (t < HIDDEN) {
        float w1x = W1[t], w1y = W1[HIDDEN + t], w1z = W1[2 * HIDDEN + t], bb = b1[t];
        float* p = (float*)&sW1[2 * t];
        p[0] = w1x; p[1] = w1x; p[2] = w1y; p[3] = w1y;
        p[4] = w1z; p[5] = w1z; p[6] = bb;  p[7] = bb;
        float u = W2[3 * t], v = W2[3 * t + 1], w = W2[3 * t + 2];
        float* q = (float*)&sW2[t];
        q[0] = u; q[1] = u; q[2] = v; q[3] = v;
        ((u64*)sW22)[t] = pk(w, w);
    }
    __syncthreads();

    int i = blockIdx.x * blockDim.x + t;   // octet index: rays 8i .. 8i+7
    if (i >= n_oct) return;

    float cx = center[0], cy = center[1], cz = center[2];
    float rad = radius[0];

    // Load 8 rays (24 floats) as 6 float4 each stream, fully coalesced.
    float fo[24], fd[24];
    {
        const float4* og = (const float4*)origins;
        const float4* dg = (const float4*)directions;
        #pragma unroll
        for (int k = 0; k < 6; ++k) {
            ((float4*)fo)[k] = og[6 * i + k];
            ((float4*)fd)[k] = dg[6 * i + k];
        }
    }

    // Pair p covers rays 2p, 2p+1: component c of ray r is f[3r+c].
    u64 qx[NPAIR], qy[NPAIR], qz[NPAIR], vx[NPAIR], vy[NPAIR], vz[NPAIR];
    #pragma unroll
    for (int p = 0; p < NPAIR; ++p) {
        qx[p] = pk(fo[6 * p + 0] - cx, fo[6 * p + 3] - cx);
        qy[p] = pk(fo[6 * p + 1] - cy, fo[6 * p + 4] - cy);
        qz[p] = pk(fo[6 * p + 2] - cz, fo[6 * p + 5] - cz);
        vx[p] = pk(fd[6 * p + 0], fd[6 * p + 3]);
        vy[p] = pk(fd[6 * p + 1], fd[6 * p + 4]);
        vz[p] = pk(fd[6 * p + 2], fd[6 * p + 5]);
    }

    float s[2 * NPAIR], pv[2 * NPAIR];
    #pragma unroll
    for (int r = 0; r < 2 * NPAIR; ++r) { s[r] = 0.f; pv[r] = 1e30f; }

    #pragma unroll 1
    for (int blk = 0; blk < N_BLKS; ++blk) {
        #pragma unroll
        for (int u = 0; u < 4; ++u) {
            #pragma unroll
            for (int p = 0; p < NPAIR; ++p) {
                u64 n2 = fma2(qx[p], qx[p], fma2(qy[p], qy[p], mul2(qz[p], qz[p])));
                float n0, n1; upk(n2, n0, n1);
                s[2 * p]     = sqap(n0) - rad;
                s[2 * p + 1] = sqap(n1) - rad;
                u64 s2 = pk(s[2 * p], s[2 * p + 1]);
                qx[p] = fma2(s2, vx[p], qx[p]);
                qy[p] = fma2(s2, vy[p], qy[p]);
                qz[p] = fma2(s2, vz[p], qz[p]);
            }
        }
        // Done = converged hit (mask guaranteed 1) or past-perigee miss
        // (mask guaranteed 0). Exit when all 8 rays of this thread are done.
        bool all_done = true;
        #pragma unroll
        for (int r = 0; r < 2 * NPAIR; ++r) {
            bool d = (s[r] < EPS_HIT) | ((s[r] > pv[r]) & (s[r] > EPS_MISS));
            all_done &= d;
            pv[r] = s[r];
        }
        if (all_done) break;
    }

    bool m[2 * NPAIR];
    #pragma unroll
    for (int r = 0; r < 2 * NPAIR; ++r) m[r] = s[r] < SDF_EPS;

    // points = q + center (reuse q arrays as p)
    u64 cX = pk(cx, cx), cY = pk(cy, cy), cZ = pk(cz, cz);
    #pragma unroll
    for (int p = 0; p < NPAIR; ++p) {
        qx[p] = add2(qx[p], cX);
        qy[p] = add2(qy[p], cY);
        qz[p] = add2(qz[p], cZ);
    }

    float bo0 = b2[0], bo1 = b2[1], bo2 = b2[2];
    u64 a0[NPAIR], a1[NPAIR], a2[NPAIR];
    #pragma unroll
    for (int p = 0; p < NPAIR; ++p) {
        a0[p] = pk(bo0, bo0);
        a1[p] = pk(bo1, bo1);
        a2[p] = pk(bo2, bo2);
    }

    #pragma unroll 2
    for (int w = 0; w < HIDDEN / 2; ++w) {
        // hidden units j = 2w (even) and 2w+1 (odd): 7 LDS.128 serve 8 rays
        ulonglong2 wA0 = sW1[4 * w + 0];
        ulonglong2 wB0 = sW1[4 * w + 1];
        ulonglong2 wA1 = sW1[4 * w + 2];
        ulonglong2 wB1 = sW1[4 * w + 3];
        ulonglong2 uA0 = sW2[2 * w + 0];
        ulonglong2 uA1 = sW2[2 * w + 1];
        ulonglong2 w22 = sW22[w];          // .x = j even, .y = j odd

        #pragma unroll
        for (int p = 0; p < NPAIR; ++p) {
            u64 h = fma2(qx[p], wA0.x, fma2(qy[p], wA0.y, fma2(qz[p], wB0.x, wB0.y)));
            h = relu2(h);
            a0[p] = fma2(h, uA0.x, a0[p]);
            a1[p] = fma2(h, uA0.y, a1[p]);
            a2[p] = fma2(h, w22.x, a2[p]);

            u64 g = fma2(qx[p], wA1.x, fma2(qy[p], wA1.y, fma2(qz[p], wB1.x, wB1.y)));
            g = relu2(g);
            a0[p] = fma2(g, uA1.x, a0[p]);
            a1[p] = fma2(g, uA1.y, a1[p]);
            a2[p] = fma2(g, w22.y, a2[p]);
        }
    }

    // Unpack, sigmoid, mask, store: 24 floats = 6 float4.
    float res[24];
    #pragma unroll
    for (int p = 0; p < NPAIR; ++p) {
        float c0a, c0b, c1a, c1b, c2a, c2b;
        upk(a0[p], c0a, c0b);
        upk(a1[p], c1a, c1b);
        upk(a2[p], c2a, c2b);
        res[6 * p + 0] = m[2 * p]     ? sgm(c0a) : 0.f;
        res[6 * p + 1] = m[2 * p]     ? sgm(c1a) : 0.f;
        res[6 * p + 2] = m[2 * p]     ? sgm(c2a) : 0.f;
        res[6 * p + 3] = m[2 * p + 1] ? sgm(c0b) : 0.f;
        res[6 * p + 4] = m[2 * p + 1] ? sgm(c1b) : 0.f;
        res[6 * p + 5] = m[2 * p + 1] ? sgm(c2b) : 0.f;
    }
    float4* o4 = (float4*)out;
    #pragma unroll
    for (int k = 0; k < 6; ++k)
        o4[6 * i + k] = ((float4*)res)[k];
}

extern "C" void kernel_launch(void* const* d_in, const int* in_sizes, int n_in,
                              void* d_out, int out_size) {
    const float* origins    = (const float*)d_in[0];
    const float* directions = (const float*)d_in[1];
    const float* center     = (const float*)d_in[2];
    const float* radius     = (const float*)d_in[3];
    const float* W1         = (const float*)d_in[4];
    const float* b1         = (const float*)d_in[5];
    const float* W2         = (const float*)d_in[6];
    const float* b2         = (const float*)d_in[7];
    float* out = (float*)d_out;

    int n_rays = in_sizes[0] / 3;
    int n_oct = n_rays / 8;
    int block = 256;
    int grid = (n_oct + block - 1) / block;
    sphere_trace_kernel<<<grid, block>>>(origins, directions, center, radius,
                                         W1, b1, W2, b2, out, n_oct);
}

// round 8
// speedup vs baseline: 1.2303x; 1.1478x over previous
#include <cuda_runtime.h>
#include <cuda_bf16.h>

// SphereTracingRenderer: fused 64-iter sphere trace + 3->128->3 MLP, masked.
// Trace: R2 structure, 4 rays/thread as two ray-packed f32x2 pairs, early exit.
// MLP: UNIT-PACKED f32x2 — weights stored once as {w_j, w_j+1} pairs
// (4 LDS.128 per 2 hidden units, vs 7 with duplicated ray-packed weights);
// point coords broadcast-packed {px,px} once per ray. Same MAC count.

#define N_BLKS 16           // 16 blocks x 4 iters = 64
#define HIDDEN 128
#define SDF_EPS 1e-4f
#define EPS_HIT 5e-5f       // s < this => final s63 < SDF_EPS (monotone decrease)
#define EPS_MISS 2e-4f      // s increasing and > this => final s63 > SDF_EPS

typedef unsigned long long u64;

__device__ __forceinline__ u64 pk(float a, float b) {
    u64 r; asm("mov.b64 %0,{%1,%2};" : "=l"(r) : "f"(a), "f"(b)); return r;
}
__device__ __forceinline__ void upk(u64 v, float& a, float& b) {
    asm("mov.b64 {%0,%1},%2;" : "=f"(a), "=f"(b) : "l"(v));
}
__device__ __forceinline__ u64 fma2(u64 a, u64 b, u64 c) {
    u64 d; asm("fma.rn.f32x2 %0,%1,%2,%3;" : "=l"(d) : "l"(a), "l"(b), "l"(c)); return d;
}
__device__ __forceinline__ u64 mul2(u64 a, u64 b) {
    u64 d; asm("mul.rn.f32x2 %0,%1,%2;" : "=l"(d) : "l"(a), "l"(b)); return d;
}
__device__ __forceinline__ u64 add2(u64 a, u64 b) {
    u64 d; asm("add.rn.f32x2 %0,%1,%2;" : "=l"(d) : "l"(a), "l"(b)); return d;
}
__device__ __forceinline__ float sqap(float x) {
    float r; asm("sqrt.approx.f32 %0,%1;" : "=f"(r) : "f"(x)); return r;
}
__device__ __forceinline__ float rcpa(float x) {
    float r; asm("rcp.approx.f32 %0,%1;" : "=f"(r) : "f"(x)); return r;
}
__device__ __forceinline__ float sgm(float x) {
    return rcpa(1.0f + __expf(-x));
}
__device__ __forceinline__ u64 relu2(u64 h) {
    float h0, h1; upk(h, h0, h1);
    return pk(fmaxf(h0, 0.f), fmaxf(h1, 0.f));
}

__global__ void __launch_bounds__(256)
sphere_trace_kernel(const float* __restrict__ origins,
                    const float* __restrict__ directions,
                    const float* __restrict__ center,
                    const float* __restrict__ radius,
                    const float* __restrict__ W1,
                    const float* __restrict__ b1,
                    const float* __restrict__ W2,
                    const float* __restrict__ b2,
                    float* __restrict__ out,
                    int n_quads)
{
    // Unit-packed weight blocks: block b covers hidden units j0=2b, j1=2b+1.
    //   sB[b][0] = { {w1x_j0,w1x_j1}, {w1y_j0,w1y_j1} }
    //   sB[b][1] = { {w1z_j0,w1z_j1}, {b1_j0, b1_j1 } }
    //   sB[b][2] = { {w20_j0,w20_j1}, {w21_j0,w21_j1} }
    //   sB[b][3] = { {w22_j0,w22_j1}, 0 }
    __shared__ ulonglong2 sB[HIDDEN / 2][4];

    int t = threadIdx.x;
    if (t < HIDDEN / 2) {
        int j0 = 2 * t, j1 = 2 * t + 1;
        sB[t][0].x = pk(W1[j0],           W1[j1]);
        sB[t][0].y = pk(W1[HIDDEN + j0],  W1[HIDDEN + j1]);
        sB[t][1].x = pk(W1[2*HIDDEN + j0], W1[2*HIDDEN + j1]);
        sB[t][1].y = pk(b1[j0],           b1[j1]);
        sB[t][2].x = pk(W2[3*j0 + 0],     W2[3*j1 + 0]);
        sB[t][2].y = pk(W2[3*j0 + 1],     W2[3*j1 + 1]);
        sB[t][3].x = pk(W2[3*j0 + 2],     W2[3*j1 + 2]);
        sB[t][3].y = 0ull;
    }
    __syncthreads();

    int i = blockIdx.x * blockDim.x + t;   // quad index: rays 4i .. 4i+3
    if (i >= n_quads) return;

    float cx = center[0], cy = center[1], cz = center[2];
    float rad = radius[0];

    // Load 4 rays (12 floats) as 3 float4, fully coalesced.
    const float4* og = (const float4*)origins;
    const float4* dg = (const float4*)directions;
    float4 A = og[3 * i], B = og[3 * i + 1], C = og[3 * i + 2];
    float4 DA = dg[3 * i], DB = dg[3 * i + 1], DC = dg[3 * i + 2];
    // ray0=(A.x,A.y,A.z) ray1=(A.w,B.x,B.y) ray2=(B.z,B.w,C.x) ray3=(C.y,C.z,C.w)

    // ---- Trace: ray-packed pairs P = rays {0,1}, Q = rays {2,3} ----
    u64 qxP = pk(A.x - cx, A.w - cx);
    u64 qyP = pk(A.y - cy, B.x - cy);
    u64 qzP = pk(A.z - cz, B.y - cz);
    u64 qxQ = pk(B.z - cx, C.y - cx);
    u64 qyQ = pk(B.w - cy, C.z - cy);
    u64 qzQ = pk(C.x - cz, C.w - cz);
    u64 vxP = pk(DA.x, DA.w), vyP = pk(DA.y, DB.x), vzP = pk(DA.z, DB.y);
    u64 vxQ = pk(DB.z, DC.y), vyQ = pk(DB.w, DC.z), vzQ = pk(DC.x, DC.w);

    float sP0 = 0.f, sP1 = 0.f, sQ0 = 0.f, sQ1 = 0.f;
    float pP0 = 1e30f, pP1 = 1e30f, pQ0 = 1e30f, pQ1 = 1e30f;

    #pragma unroll 1
    for (int blk = 0; blk < N_BLKS; ++blk) {
        #pragma unroll
        for (int u = 0; u < 4; ++u) {
            u64 nP = fma2(qxP, qxP, fma2(qyP, qyP, mul2(qzP, qzP)));
            u64 nQ = fma2(qxQ, qxQ, fma2(qyQ, qyQ, mul2(qzQ, qzQ)));
            float n0, n1; upk(nP, n0, n1);
            sP0 = sqap(n0) - rad;
            sP1 = sqap(n1) - rad;
            float n2, n3; upk(nQ, n2, n3);
            sQ0 = sqap(n2) - rad;
            sQ1 = sqap(n3) - rad;
            u64 s2P = pk(sP0, sP1);
            u64 s2Q = pk(sQ0, sQ1);
            qxP = fma2(s2P, vxP, qxP);
            qyP = fma2(s2P, vyP, qyP);
            qzP = fma2(s2P, vzP, qzP);
            qxQ = fma2(s2Q, vxQ, qxQ);
            qyQ = fma2(s2Q, vyQ, qyQ);
            qzQ = fma2(s2Q, vzQ, qzQ);
        }
        // Done = converged hit (mask guaranteed 1) or past-perigee miss
        // (mask guaranteed 0). Exit when all 4 rays of this thread are done.
        bool d0 = (sP0 < EPS_HIT) | ((sP0 > pP0) & (sP0 > EPS_MISS));
        bool d1 = (sP1 < EPS_HIT) | ((sP1 > pP1) & (sP1 > EPS_MISS));
        bool d2 = (sQ0 < EPS_HIT) | ((sQ0 > pQ0) & (sQ0 > EPS_MISS));
        bool d3 = (sQ1 < EPS_HIT) | ((sQ1 > pQ1) & (sQ1 > EPS_MISS));
        if (d0 & d1 & d2 & d3) break;
        pP0 = sP0; pP1 = sP1; pQ0 = sQ0; pQ1 = sQ1;
    }
    bool m0 = sP0 < SDF_EPS;
    bool m1 = sP1 < SDF_EPS;
    bool m2 = sQ0 < SDF_EPS;
    bool m3 = sQ1 < SDF_EPS;

    // ---- MLP: unit-packed. Broadcast point pairs {p,p} per ray. ----
    float p0x, p1x, p2x, p3x, p0y, p1y, p2y, p3y, p0z, p1z, p2z, p3z;
    upk(qxP, p0x, p1x); upk(qxQ, p2x, p3x);
    upk(qyP, p0y, p1y); upk(qyQ, p2y, p3y);
    upk(qzP, p0z, p1z); upk(qzQ, p2z, p3z);
    u64 Bx0 = pk(p0x + cx, p0x + cx), Bx1 = pk(p1x + cx, p1x + cx);
    u64 Bx2 = pk(p2x + cx, p2x + cx), Bx3 = pk(p3x + cx, p3x + cx);
    u64 By0 = pk(p0y + cy, p0y + cy), By1 = pk(p1y + cy, p1y + cy);
    u64 By2 = pk(p2y + cy, p2y + cy), By3 = pk(p3y + cy, p3y + cy);
    u64 Bz0 = pk(p0z + cz, p0z + cz), Bz1 = pk(p1z + cz, p1z + cz);
    u64 Bz2 = pk(p2z + cz, p2z + cz), Bz3 = pk(p3z + cz, p3z + cz);

    float bo0 = b2[0], bo1 = b2[1], bo2 = b2[2];
    // Bias folded into lane 0 of each accumulator pair (horizontal add at end).
    u64 A00 = pk(bo0, 0.f), A01 = pk(bo1, 0.f), A02 = pk(bo2, 0.f);
    u64 A10 = A00, A11 = A01, A12 = A02;
    u64 A20 = A00, A21 = A01, A22 = A02;
    u64 A30 = A00, A31 = A01, A32 = A02;

    #pragma unroll 4
    for (int b = 0; b < HIDDEN / 2; ++b) {
        ulonglong2 L0 = sB[b][0];   // {w1x2, w1y2}
        ulonglong2 L1 = sB[b][1];   // {w1z2, b1_2}
        ulonglong2 L2 = sB[b][2];   // {w20_2, w21_2}
        ulonglong2 L3 = sB[b][3];   // {w22_2, 0}

        u64 h0 = relu2(fma2(Bx0, L0.x, fma2(By0, L0.y, fma2(Bz0, L1.x, L1.y))));
        u64 h1 = relu2(fma2(Bx1, L0.x, fma2(By1, L0.y, fma2(Bz1, L1.x, L1.y))));
        u64 h2 = relu2(fma2(Bx2, L0.x, fma2(By2, L0.y, fma2(Bz2, L1.x, L1.y))));
        u64 h3 = relu2(fma2(Bx3, L0.x, fma2(By3, L0.y, fma2(Bz3, L1.x, L1.y))));

        A00 = fma2(h0, L2.x, A00); A01 = fma2(h0, L2.y, A01); A02 = fma2(h0, L3.x, A02);
        A10 = fma2(h1, L2.x, A10); A11 = fma2(h1, L2.y, A11); A12 = fma2(h1, L3.x, A12);
        A20 = fma2(h2, L2.x, A20); A21 = fma2(h2, L2.y, A21); A22 = fma2(h2, L3.x, A22);
        A30 = fma2(h3, L2.x, A30); A31 = fma2(h3, L2.y, A31); A32 = fma2(h3, L3.x, A32);
    }

    // Horizontal sums (bias already in lane 0), sigmoid, mask, store.
    float lo, hi;
    float x00, x01, x02, x10, x11, x12, x20, x21, x22, x30, x31, x32;
    upk(A00, lo, hi); x00 = lo + hi;
    upk(A01, lo, hi); x01 = lo + hi;
    upk(A02, lo, hi); x02 = lo + hi;
    upk(A10, lo, hi); x10 = lo + hi;
    upk(A11, lo, hi); x11 = lo + hi;
    upk(A12, lo, hi); x12 = lo + hi;
    upk(A20, lo, hi); x20 = lo + hi;
    upk(A21, lo, hi); x21 = lo + hi;
    upk(A22, lo, hi); x22 = lo + hi;
    upk(A30, lo, hi); x30 = lo + hi;
    upk(A31, lo, hi); x31 = lo + hi;
    upk(A32, lo, hi); x32 = lo + hi;

    float r0c0 = m0 ? sgm(x00) : 0.f, r0c1 = m0 ? sgm(x01) : 0.f, r0c2 = m0 ? sgm(x02) : 0.f;
    float r1c0 = m1 ? sgm(x10) : 0.f, r1c1 = m1 ? sgm(x11) : 0.f, r1c2 = m1 ? sgm(x12) : 0.f;
    float r2c0 = m2 ? sgm(x20) : 0.f, r2c1 = m2 ? sgm(x21) : 0.f, r2c2 = m2 ? sgm(x22) : 0.f;
    float r3c0 = m3 ? sgm(x30) : 0.f, r3c1 = m3 ? sgm(x31) : 0.f, r3c2 = m3 ? sgm(x32) : 0.f;

    float4* o4 = (float4*)out;
    o4[3 * i]     = make_float4(r0c0, r0c1, r0c2, r1c0);
    o4[3 * i + 1] = make_float4(r1c1, r1c2, r2c0, r2c1);
    o4[3 * i + 2] = make_float4(r2c2, r3c0, r3c1, r3c2);
}

extern "C" void kernel_launch(void* const* d_in, const int* in_sizes, int n_in,
                              void* d_out, int out_size) {
    const float* origins    = (const float*)d_in[0];
    const float* directions = (const float*)d_in[1];
    const float* center     = (const float*)d_in[2];
    const float* radius     = (const float*)d_in[3];
    const float* W1         = (const float*)d_in[4];
    const float* b1         = (const float*)d_in[5];
    const float* W2         = (const float*)d_in[6];
    const float* b2         = (const float*)d_in[7];
    float* out = (float*)d_out;

    int n_rays = in_sizes[0] / 3;
    int n_quads = n_rays / 4;
    int block = 256;
    int grid = (n_quads + block - 1) / block;
    sphere_trace_kernel<<<grid, block>>>(origins, directions, center, radius,
                                         W1, b1, W2, b2, out, n_quads);
}

// round 9
// speedup vs baseline: 1.2382x; 1.0064x over previous
#include <cuda_runtime.h>
#include <cuda_bf16.h>

// SphereTracingRenderer: fused 64-iter sphere trace + 3->128->3 MLP, masked.
// Trace: 4 rays/thread as two ray-packed f32x2 pairs, early exit (monotone SDF).
// MLP: unit-packed f32x2 ({w_j,w_j+1} pairs, 4 LDS.128 per 2 hidden units),
// run directly on CENTERED coords q: center folded into layer-1 bias
// (b1' = b1 + W1·c) at smem stage -> no post-trace center add, -6 live regs.
// __launch_bounds__(256,4): 64-reg cap -> 4 CTAs/SM.

#define N_BLKS 16           // 16 blocks x 4 iters = 64
#define HIDDEN 128
#define SDF_EPS 1e-4f
#define EPS_HIT 5e-5f       // s < this => final s63 < SDF_EPS (monotone decrease)
#define EPS_MISS 2e-4f      // s increasing and > this => final s63 > SDF_EPS

typedef unsigned long long u64;

__device__ __forceinline__ u64 pk(float a, float b) {
    u64 r; asm("mov.b64 %0,{%1,%2};" : "=l"(r) : "f"(a), "f"(b)); return r;
}
__device__ __forceinline__ void upk(u64 v, float& a, float& b) {
    asm("mov.b64 {%0,%1},%2;" : "=f"(a), "=f"(b) : "l"(v));
}
__device__ __forceinline__ u64 fma2(u64 a, u64 b, u64 c) {
    u64 d; asm("fma.rn.f32x2 %0,%1,%2,%3;" : "=l"(d) : "l"(a), "l"(b), "l"(c)); return d;
}
__device__ __forceinline__ u64 mul2(u64 a, u64 b) {
    u64 d; asm("mul.rn.f32x2 %0,%1,%2;" : "=l"(d) : "l"(a), "l"(b)); return d;
}
__device__ __forceinline__ float sqap(float x) {
    float r; asm("sqrt.approx.f32 %0,%1;" : "=f"(r) : "f"(x)); return r;
}
__device__ __forceinline__ float rcpa(float x) {
    float r; asm("rcp.approx.f32 %0,%1;" : "=f"(r) : "f"(x)); return r;
}
__device__ __forceinline__ float sgm(float x) {
    return rcpa(1.0f + __expf(-x));
}
__device__ __forceinline__ u64 relu2(u64 h) {
    float h0, h1; upk(h, h0, h1);
    return pk(fmaxf(h0, 0.f), fmaxf(h1, 0.f));
}

__global__ void __launch_bounds__(256, 4)
sphere_trace_kernel(const float* __restrict__ origins,
                    const float* __restrict__ directions,
                    const float* __restrict__ center,
                    const float* __restrict__ radius,
                    const float* __restrict__ W1,
                    const float* __restrict__ b1,
                    const float* __restrict__ W2,
                    const float* __restrict__ b2,
                    float* __restrict__ out,
                    int n_quads)
{
    // Unit-packed weight blocks: block b covers hidden units j0=2b, j1=2b+1.
    //   sB[b][0] = { {w1x_j0,w1x_j1}, {w1y_j0,w1y_j1} }
    //   sB[b][1] = { {w1z_j0,w1z_j1}, {b1'_j0,b1'_j1} }  (b1' = b1 + W1·c)
    //   sB[b][2] = { {w20_j0,w20_j1}, {w21_j0,w21_j1} }
    //   sB[b][3] = { {w22_j0,w22_j1}, 0 }
    __shared__ ulonglong2 sB[HIDDEN / 2][4];

    int t = threadIdx.x;
    float cx = center[0], cy = center[1], cz = center[2];
    if (t < HIDDEN / 2) {
        int j0 = 2 * t, j1 = 2 * t + 1;
        float w1x0 = W1[j0],            w1x1 = W1[j1];
        float w1y0 = W1[HIDDEN + j0],   w1y1 = W1[HIDDEN + j1];
        float w1z0 = W1[2*HIDDEN + j0], w1z1 = W1[2*HIDDEN + j1];
        // center folded into bias: b1' = b1 + w1x*cx + w1y*cy + w1z*cz
        float bb0 = b1[j0] + w1x0 * cx + w1y0 * cy + w1z0 * cz;
        float bb1 = b1[j1] + w1x1 * cx + w1y1 * cy + w1z1 * cz;
        sB[t][0].x = pk(w1x0, w1x1);
        sB[t][0].y = pk(w1y0, w1y1);
        sB[t][1].x = pk(w1z0, w1z1);
        sB[t][1].y = pk(bb0,  bb1);
        sB[t][2].x = pk(W2[3*j0 + 0], W2[3*j1 + 0]);
        sB[t][2].y = pk(W2[3*j0 + 1], W2[3*j1 + 1]);
        sB[t][3].x = pk(W2[3*j0 + 2], W2[3*j1 + 2]);
        sB[t][3].y = 0ull;
    }
    __syncthreads();

    int i = blockIdx.x * blockDim.x + t;   // quad index: rays 4i .. 4i+3
    if (i >= n_quads) return;

    float rad = radius[0];

    // Load 4 rays (12 floats) as 3 float4, fully coalesced.
    const float4* og = (const float4*)origins;
    const float4* dg = (const float4*)directions;
    float4 A = og[3 * i], B = og[3 * i + 1], C = og[3 * i + 2];
    float4 DA = dg[3 * i], DB = dg[3 * i + 1], DC = dg[3 * i + 2];
    // ray0=(A.x,A.y,A.z) ray1=(A.w,B.x,B.y) ray2=(B.z,B.w,C.x) ray3=(C.y,C.z,C.w)

    // ---- Trace: ray-packed pairs P = rays {0,1}, Q = rays {2,3} ----
    u64 qxP = pk(A.x - cx, A.w - cx);
    u64 qyP = pk(A.y - cy, B.x - cy);
    u64 qzP = pk(A.z - cz, B.y - cz);
    u64 qxQ = pk(B.z - cx, C.y - cx);
    u64 qyQ = pk(B.w - cy, C.z - cy);
    u64 qzQ = pk(C.x - cz, C.w - cz);
    u64 vxP = pk(DA.x, DA.w), vyP = pk(DA.y, DB.x), vzP = pk(DA.z, DB.y);
    u64 vxQ = pk(DB.z, DC.y), vyQ = pk(DB.w, DC.z), vzQ = pk(DC.x, DC.w);

    float sP0 = 0.f, sP1 = 0.f, sQ0 = 0.f, sQ1 = 0.f;
    float pP0 = 1e30f, pP1 = 1e30f, pQ0 = 1e30f, pQ1 = 1e30f;

    #pragma unroll 1
    for (int blk = 0; blk < N_BLKS; ++blk) {
        #pragma unroll
        for (int u = 0; u < 4; ++u) {
            u64 nP = fma2(qxP, qxP, fma2(qyP, qyP, mul2(qzP, qzP)));
            u64 nQ = fma2(qxQ, qxQ, fma2(qyQ, qyQ, mul2(qzQ, qzQ)));
            float n0, n1; upk(nP, n0, n1);
            sP0 = sqap(n0) - rad;
            sP1 = sqap(n1) - rad;
            float n2, n3; upk(nQ, n2, n3);
            sQ0 = sqap(n2) - rad;
            sQ1 = sqap(n3) - rad;
            u64 s2P = pk(sP0, sP1);
            u64 s2Q = pk(sQ0, sQ1);
            qxP = fma2(s2P, vxP, qxP);
            qyP = fma2(s2P, vyP, qyP);
            qzP = fma2(s2P, vzP, qzP);
            qxQ = fma2(s2Q, vxQ, qxQ);
            qyQ = fma2(s2Q, vyQ, qyQ);
            qzQ = fma2(s2Q, vzQ, qzQ);
        }
        // Done = converged hit (mask guaranteed 1) or past-perigee miss
        // (mask guaranteed 0). Exit when all 4 rays of this thread are done.
        bool d0 = (sP0 < EPS_HIT) | ((sP0 > pP0) & (sP0 > EPS_MISS));
        bool d1 = (sP1 < EPS_HIT) | ((sP1 > pP1) & (sP1 > EPS_MISS));
        bool d2 = (sQ0 < EPS_HIT) | ((sQ0 > pQ0) & (sQ0 > EPS_MISS));
        bool d3 = (sQ1 < EPS_HIT) | ((sQ1 > pQ1) & (sQ1 > EPS_MISS));
        if (d0 & d1 & d2 & d3) break;
        pP0 = sP0; pP1 = sP1; pQ0 = sQ0; pQ1 = sQ1;
    }
    bool m0 = sP0 < SDF_EPS;
    bool m1 = sP1 < SDF_EPS;
    bool m2 = sQ0 < SDF_EPS;
    bool m3 = sQ1 < SDF_EPS;

    // ---- MLP on centered coords (bias carries W1·c). Broadcast {q,q}. ----
    float p0x, p1x, p2x, p3x, p0y, p1y, p2y, p3y, p0z, p1z, p2z, p3z;
    upk(qxP, p0x, p1x); upk(qxQ, p2x, p3x);
    upk(qyP, p0y, p1y); upk(qyQ, p2y, p3y);
    upk(qzP, p0z, p1z); upk(qzQ, p2z, p3z);
    u64 Bx0 = pk(p0x, p0x), Bx1 = pk(p1x, p1x);
    u64 Bx2 = pk(p2x, p2x), Bx3 = pk(p3x, p3x);
    u64 By0 = pk(p0y, p0y), By1 = pk(p1y, p1y);
    u64 By2 = pk(p2y, p2y), By3 = pk(p3y, p3y);
    u64 Bz0 = pk(p0z, p0z), Bz1 = pk(p1z, p1z);
    u64 Bz2 = pk(p2z, p2z), Bz3 = pk(p3z, p3z);

    float bo0 = b2[0], bo1 = b2[1], bo2 = b2[2];
    // Bias folded into lane 0 of each accumulator pair (horizontal add at end).
    u64 A00 = pk(bo0, 0.f), A01 = pk(bo1, 0.f), A02 = pk(bo2, 0.f);
    u64 A10 = A00, A11 = A01, A12 = A02;
    u64 A20 = A00, A21 = A01, A22 = A02;
    u64 A30 = A00, A31 = A01, A32 = A02;

    #pragma unroll 4
    for (int b = 0; b < HIDDEN / 2; ++b) {
        ulonglong2 L0 = sB[b][0];   // {w1x2, w1y2}
        ulonglong2 L1 = sB[b][1];   // {w1z2, b1'2}
        ulonglong2 L2 = sB[b][2];   // {w20_2, w21_2}
        ulonglong2 L3 = sB[b][3];   // {w22_2, 0}

        u64 h0 = relu2(fma2(Bx0, L0.x, fma2(By0, L0.y, fma2(Bz0, L1.x, L1.y))));
        u64 h1 = relu2(fma2(Bx1, L0.x, fma2(By1, L0.y, fma2(Bz1, L1.x, L1.y))));
        u64 h2 = relu2(fma2(Bx2, L0.x, fma2(By2, L0.y, fma2(Bz2, L1.x, L1.y))));
        u64 h3 = relu2(fma2(Bx3, L0.x, fma2(By3, L0.y, fma2(Bz3, L1.x, L1.y))));

        A00 = fma2(h0, L2.x, A00); A01 = fma2(h0, L2.y, A01); A02 = fma2(h0, L3.x, A02);
        A10 = fma2(h1, L2.x, A10); A11 = fma2(h1, L2.y, A11); A12 = fma2(h1, L3.x, A12);
        A20 = fma2(h2, L2.x, A20); A21 = fma2(h2, L2.y, A21); A22 = fma2(h2, L3.x, A22);
        A30 = fma2(h3, L2.x, A30); A31 = fma2(h3, L2.y, A31); A32 = fma2(h3, L3.x, A32);
    }

    // Horizontal sums (bias already in lane 0), sigmoid, mask, store.
    float lo, hi;
    float x00, x01, x02, x10, x11, x12, x20, x21, x22, x30, x31, x32;
    upk(A00, lo, hi); x00 = lo + hi;
    upk(A01, lo, hi); x01 = lo + hi;
    upk(A02, lo, hi); x02 = lo + hi;
    upk(A10, lo, hi); x10 = lo + hi;
    upk(A11, lo, hi); x11 = lo + hi;
    upk(A12, lo, hi); x12 = lo + hi;
    upk(A20, lo, hi); x20 = lo + hi;
    upk(A21, lo, hi); x21 = lo + hi;
    upk(A22, lo, hi); x22 = lo + hi;
    upk(A30, lo, hi); x30 = lo + hi;
    upk(A31, lo, hi); x31 = lo + hi;
    upk(A32, lo, hi); x32 = lo + hi;

    float r0c0 = m0 ? sgm(x00) : 0.f, r0c1 = m0 ? sgm(x01) : 0.f, r0c2 = m0 ? sgm(x02) : 0.f;
    float r1c0 = m1 ? sgm(x10) : 0.f, r1c1 = m1 ? sgm(x11) : 0.f, r1c2 = m1 ? sgm(x12) : 0.f;
    float r2c0 = m2 ? sgm(x20) : 0.f, r2c1 = m2 ? sgm(x21) : 0.f, r2c2 = m2 ? sgm(x22) : 0.f;
    float r3c0 = m3 ? sgm(x30) : 0.f, r3c1 = m3 ? sgm(x31) : 0.f, r3c2 = m3 ? sgm(x32) : 0.f;

    float4* o4 = (float4*)out;
    o4[3 * i]     = make_float4(r0c0, r0c1, r0c2, r1c0);
    o4[3 * i + 1] = make_float4(r1c1, r1c2, r2c0, r2c1);
    o4[3 * i + 2] = make_float4(r2c2, r3c0, r3c1, r3c2);
}

extern "C" void kernel_launch(void* const* d_in, const int* in_sizes, int n_in,
                              void* d_out, int out_size) {
    const float* origins    = (const float*)d_in[0];
    const float* directions = (const float*)d_in[1];
    const float* center     = (const float*)d_in[2];
    const float* radius     = (const float*)d_in[3];
    const float* W1         = (const float*)d_in[4];
    const float* b1         = (const float*)d_in[5];
    const float* W2         = (const float*)d_in[6];
    const float* b2         = (const float*)d_in[7];
    float* out = (float*)d_out;

    int n_rays = in_sizes[0] / 3;
    int n_quads = n_rays / 4;
    int block = 256;
    int grid = (n_quads + block - 1) / block;
    sphere_trace_kernel<<<grid, block>>>(origins, directions, center, radius,
                                         W1, b1, W2, b2, out, n_quads);
}

// round 10
// speedup vs baseline: 1.6254x; 1.3127x over previous
#include <cuda_runtime.h>
#include <cuda_fp16.h>

// SphereTracingRenderer: fused 64-iter sphere trace + 3->128->3 MLP, masked.
// Trace: 4 rays/thread, two ray-packed f32x2 pairs, early exit (monotone SDF).
// MLP: TENSOR CORES (warp mma.sync, fp16 in / fp32 accum):
//   per 16-ray tile, per 16-hidden ktile:
//     L1: 2x mma.m16n8k8  (P-frag x W1-frag) -> D1 fragments
//     D1 -> relu -> cvt f16x2  == A-fragment of L2 (flash-attn chaining)
//     L2: 1x mma.m16n8k16 accumulate into per-channel fp32 accums
// Weights pre-baked as lane-indexed fragment tables in smem. Center folded
// into L1 bias column. Warp-local staging: each warp's 128 traced rays are
// its own 8 mma tiles (no block barrier between phases).

#define N_BLKS 16           // 16 x 4 iters = 64
#define HIDDEN 128
#define SDF_EPS 1e-4f
#define EPS_HIT 5e-5f
#define EPS_MISS 2e-4f

typedef unsigned long long u64;
typedef unsigned int u32;

__device__ __forceinline__ u64 pk(float a, float b) {
    u64 r; asm("mov.b64 %0,{%1,%2};" : "=l"(r) : "f"(a), "f"(b)); return r;
}
__device__ __forceinline__ void upk(u64 v, float& a, float& b) {
    asm("mov.b64 {%0,%1},%2;" : "=f"(a), "=f"(b) : "l"(v));
}
__device__ __forceinline__ u64 fma2(u64 a, u64 b, u64 c) {
    u64 d; asm("fma.rn.f32x2 %0,%1,%2,%3;" : "=l"(d) : "l"(a), "l"(b), "l"(c)); return d;
}
__device__ __forceinline__ u64 mul2(u64 a, u64 b) {
    u64 d; asm("mul.rn.f32x2 %0,%1,%2;" : "=l"(d) : "l"(a), "l"(b)); return d;
}
__device__ __forceinline__ float sqap(float x) {
    float r; asm("sqrt.approx.f32 %0,%1;" : "=f"(r) : "f"(x)); return r;
}
__device__ __forceinline__ float rcpa(float x) {
    float r; asm("rcp.approx.f32 %0,%1;" : "=f"(r) : "f"(x)); return r;
}
__device__ __forceinline__ float sgm(float x) {
    return rcpa(1.0f + __expf(-x));
}
// {hi, lo} -> f16x2 (first PTX source is the HIGH half)
__device__ __forceinline__ u32 cvt2(float hi, float lo) {
    u32 r; asm("cvt.rn.f16x2.f32 %0,%1,%2;" : "=r"(r) : "f"(hi), "f"(lo)); return r;
}
__device__ __forceinline__ u32 hmax0(u32 a) {   // relu on f16x2
    u32 r; asm("max.f16x2 %0,%1,%2;" : "=r"(r) : "r"(a), "r"(0u)); return r;
}
__device__ __forceinline__ void mma1688(float& d0, float& d1, float& d2, float& d3,
                                        u32 a0, u32 a1, u32 b) {
    asm("mma.sync.aligned.m16n8k8.row.col.f32.f16.f16.f32 "
        "{%0,%1,%2,%3},{%4,%5},{%6},{%7,%8,%9,%10};"
        : "=f"(d0), "=f"(d1), "=f"(d2), "=f"(d3)
        : "r"(a0), "r"(a1), "r"(b), "f"(0.f), "f"(0.f), "f"(0.f), "f"(0.f));
}
__device__ __forceinline__ void mma16816(float& c0, float& c1, float& c2, float& c3,
                                         u32 a0, u32 a1, u32 a2, u32 a3,
                                         u32 b0, u32 b1) {
    asm("mma.sync.aligned.m16n8k16.row.col.f32.f16.f16.f32 "
        "{%0,%1,%2,%3},{%4,%5,%6,%7},{%8,%9},{%0,%1,%2,%3};"
        : "+f"(c0), "+f"(c1), "+f"(c2), "+f"(c3)
        : "r"(a0), "r"(a1), "r"(a2), "r"(a3), "r"(b0), "r"(b1));
}

__global__ void __launch_bounds__(256)
sphere_trace_kernel(const float* __restrict__ origins,
                    const float* __restrict__ directions,
                    const float* __restrict__ center,
                    const float* __restrict__ radius,
                    const float* __restrict__ W1,
                    const float* __restrict__ b1,
                    const float* __restrict__ W2,
                    const float* __restrict__ b2,
                    float* __restrict__ out,
                    int n_quads)
{
    __shared__ float4 sP4[1024];       // per-ray {qx,qy,qz,sdf}, warp-local use
    __shared__ u32  B1T[512];          // L1 B-frags: [kt][ntile][lane]
    __shared__ uint2 B2T[256];         // L2 B-frags: [kt][lane] -> (b0,b1)

    int t = threadIdx.x;
    float cx = center[0], cy = center[1], cz = center[2];

    // ---- Bake W1 (+bias column, center folded) into m16n8k8 B fragments ----
    // B1[k][n] for ktile kt, ntile nt: j = 16*kt + 8*nt + lane/4, k-pair = 2*(lane%4).
    // k=0..2 -> W1 row k, k=3 -> b1' = b1 + W1.c, k>=4 -> 0.
    for (int e = t; e < 512; e += 256) {
        int kt = e >> 6, nt = (e >> 5) & 1, ln = e & 31;
        int mm = ln & 3, j = 16 * kt + 8 * nt + (ln >> 2);
        float v[2];
        #pragma unroll
        for (int h = 0; h < 2; ++h) {
            int k = 2 * mm + h;
            float val = 0.f;
            if (k == 0) val = W1[j];
            else if (k == 1) val = W1[HIDDEN + j];
            else if (k == 2) val = W1[2 * HIDDEN + j];
            else if (k == 3) val = b1[j] + W1[j] * cx + W1[HIDDEN + j] * cy
                                   + W1[2 * HIDDEN + j] * cz;
            v[h] = val;
        }
        B1T[e] = cvt2(v[1], v[0]);
    }
    // ---- Bake W2 into m16n8k16 B fragments: j0 = 16*kt + 2*(lane%4), n = lane/4 ----
    for (int e = t; e < 256; e += 256) {
        int kt = e >> 5, ln = e & 31;
        int mm = ln & 3, n = ln >> 2;
        int j0 = 16 * kt + 2 * mm;
        float g0 = (n < 3) ? W2[3 * j0 + n]       : 0.f;
        float g1 = (n < 3) ? W2[3 * (j0 + 1) + n] : 0.f;
        float g8 = (n < 3) ? W2[3 * (j0 + 8) + n] : 0.f;
        float g9 = (n < 3) ? W2[3 * (j0 + 9) + n] : 0.f;
        B2T[e] = make_uint2(cvt2(g1, g0), cvt2(g9, g8));
    }
    __syncthreads();

    if (blockIdx.x * blockDim.x >= (unsigned)n_quads) return;   // uniform guard
    int i = blockIdx.x * blockDim.x + t;   // quad: rays 4i..4i+3

    float rad = radius[0];

    const float4* og = (const float4*)origins;
    const float4* dg = (const float4*)directions;
    float4 A = og[3 * i], B = og[3 * i + 1], C = og[3 * i + 2];
    float4 DA = dg[3 * i], DB = dg[3 * i + 1], DC = dg[3 * i + 2];
    // ray0=(A.x,A.y,A.z) ray1=(A.w,B.x,B.y) ray2=(B.z,B.w,C.x) ray3=(C.y,C.z,C.w)

    // ---- Trace (centered coords), ray-packed pairs P={0,1}, Q={2,3} ----
    u64 qxP = pk(A.x - cx, A.w - cx);
    u64 qyP = pk(A.y - cy, B.x - cy);
    u64 qzP = pk(A.z - cz, B.y - cz);
    u64 qxQ = pk(B.z - cx, C.y - cx);
    u64 qyQ = pk(B.w - cy, C.z - cy);
    u64 qzQ = pk(C.x - cz, C.w - cz);
    u64 vxP = pk(DA.x, DA.w), vyP = pk(DA.y, DB.x), vzP = pk(DA.z, DB.y);
    u64 vxQ = pk(DB.z, DC.y), vyQ = pk(DB.w, DC.z), vzQ = pk(DC.x, DC.w);

    float sP0 = 0.f, sP1 = 0.f, sQ0 = 0.f, sQ1 = 0.f;
    float pP0 = 1e30f, pP1 = 1e30f, pQ0 = 1e30f, pQ1 = 1e30f;

    #pragma unroll 1
    for (int blk = 0; blk < N_BLKS; ++blk) {
        #pragma unroll
        for (int u = 0; u < 4; ++u) {
            u64 nP = fma2(qxP, qxP, fma2(qyP, qyP, mul2(qzP, qzP)));
            u64 nQ = fma2(qxQ, qxQ, fma2(qyQ, qyQ, mul2(qzQ, qzQ)));
            float n0, n1; upk(nP, n0, n1);
            sP0 = sqap(n0) - rad;
            sP1 = sqap(n1) - rad;
            float n2, n3; upk(nQ, n2, n3);
            sQ0 = sqap(n2) - rad;
            sQ1 = sqap(n3) - rad;
            u64 s2P = pk(sP0, sP1);
            u64 s2Q = pk(sQ0, sQ1);
            qxP = fma2(s2P, vxP, qxP);
            qyP = fma2(s2P, vyP, qyP);
            qzP = fma2(s2P, vzP, qzP);
            qxQ = fma2(s2Q, vxQ, qxQ);
            qyQ = fma2(s2Q, vyQ, qyQ);
            qzQ = fma2(s2Q, vzQ, qzQ);
        }
        bool d0 = (sP0 < EPS_HIT) | ((sP0 > pP0) & (sP0 > EPS_MISS));
        bool d1 = (sP1 < EPS_HIT) | ((sP1 > pP1) & (sP1 > EPS_MISS));
        bool d2 = (sQ0 < EPS_HIT) | ((sQ0 > pQ0) & (sQ0 > EPS_MISS));
        bool d3 = (sQ1 < EPS_HIT) | ((sQ1 > pQ1) & (sQ1 > EPS_MISS));
        if (d0 & d1 & d2 & d3) break;
        pP0 = sP0; pP1 = sP1; pQ0 = sQ0; pQ1 = sQ1;
    }

    // ---- Stage this thread's 4 rays: {q, sdf} (warp-local consumption) ----
    {
        float x0, x1, x2, x3, y0, y1, y2, y3, z0, z1, z2, z3;
        upk(qxP, x0, x1); upk(qxQ, x2, x3);
        upk(qyP, y0, y1); upk(qyQ, y2, y3);
        upk(qzP, z0, z1); upk(qzQ, z2, z3);
        sP4[4 * t + 0] = make_float4(x0, y0, z0, sP0);
        sP4[4 * t + 1] = make_float4(x1, y1, z1, sP1);
        sP4[4 * t + 2] = make_float4(x2, y2, z2, sQ0);
        sP4[4 * t + 3] = make_float4(x3, y3, z3, sQ1);
    }
    __syncwarp();

    // ---- MLP on tensor cores: warp handles its 128 rays = 8 tiles of 16 ----
    int lane = t & 31;
    int mm = lane & 3;
    int ch0 = 2 * mm, ch1 = ch0 + 1;
    float i0 = (ch0 < 3) ? b2[ch0] : 0.f;
    float i1 = (ch1 < 3) ? b2[ch1] : 0.f;
    int wbase = (t >> 5) * 128;
    int grayB = blockIdx.x * 1024;

    #pragma unroll 1
    for (int tile = 0; tile < 8; ++tile) {
        int rA = wbase + tile * 16 + (lane >> 2);
        int rB = rA + 8;
        float4 PA = sP4[rA];
        float4 PB = sP4[rB];

        // L1 A-fragment (constant across ktiles): K = [qx,qy,qz,1,0,0,0,0]
        u32 a0 = 0, a1 = 0;
        if (mm == 0)      { a0 = cvt2(PA.y, PA.x); a1 = cvt2(PB.y, PB.x); }
        else if (mm == 1) { a0 = cvt2(1.0f, PA.z); a1 = cvt2(1.0f, PB.z); }

        float c0 = i0, c1 = i1, c2 = i0, c3 = i1;

        #pragma unroll
        for (int kt = 0; kt < 8; ++kt) {
            u32 b1a = B1T[kt * 64 + lane];
            u32 b1b = B1T[kt * 64 + 32 + lane];
            float da0, da1, da2, da3, db0, db1, db2, db3;
            mma1688(da0, da1, da2, da3, a0, a1, b1a);   // hid 16kt+0..7
            mma1688(db0, db1, db2, db3, a0, a1, b1b);   // hid 16kt+8..15
            u32 h0 = hmax0(cvt2(da1, da0));   // (rayA, k0 k1)
            u32 h1 = hmax0(cvt2(da3, da2));   // (rayB, k0 k1)
            u32 h2 = hmax0(cvt2(db1, db0));   // (rayA, k8 k9)
            u32 h3 = hmax0(cvt2(db3, db2));   // (rayB, k8 k9)
            uint2 b2f = B2T[kt * 32 + lane];
            mma16816(c0, c1, c2, c3, h0, h1, h2, h3, b2f.x, b2f.y);
        }

        // Epilogue: sigmoid + mask-select (kills inf/NaN miss rays), store.
        bool mA = PA.w < SDF_EPS;
        bool mB = PB.w < SDF_EPS;
        int gA = grayB + rA, gB = grayB + rB;
        if (ch0 < 3) {
            out[3 * gA + ch0] = mA ? sgm(c0) : 0.f;
            out[3 * gB + ch0] = mB ? sgm(c2) : 0.f;
        }
        if (ch1 < 3) {
            out[3 * gA + ch1] = mA ? sgm(c1) : 0.f;
            out[3 * gB + ch1] = mB ? sgm(c3) : 0.f;
        }
    }
}

extern "C" void kernel_launch(void* const* d_in, const int* in_sizes, int n_in,
                              void* d_out, int out_size) {
    const float* origins    = (const float*)d_in[0];
    const float* directions = (const float*)d_in[1];
    const float* center     = (const float*)d_in[2];
    const float* radius     = (const float*)d_in[3];
    const float* W1         = (const float*)d_in[4];
    const float* b1         = (const float*)d_in[5];
    const float* W2         = (const float*)d_in[6];
    const float* b2         = (const float*)d_in[7];
    float* out = (float*)d_out;

    int n_rays = in_sizes[0] / 3;
    int n_quads = n_rays / 4;
    int block = 256;
    int grid = (n_quads + block - 1) / block;
    sphere_trace_kernel<<<grid, block>>>(origins, directions, center, radius,
                                         W1, b1, W2, b2, out, n_quads);
}

// round 11
// speedup vs baseline: 1.7591x; 1.0823x over previous
#include <cuda_runtime.h>
#include <cuda_fp16.h>

// SphereTracingRenderer: fused 64-iter sphere trace + 3->128->3 MLP, masked.
// Trace: SCALAR fp32, 4 rays/thread, early exit (monotone SDF) — FFMA2 is
// rt=4 on sm_103a so packing buys nothing and costs ALU MOVs.
// MLP: tensor cores. L1 = 2x mma.m16n8k8 with F16 ACCUM — D fragments are
// f16x2-packed exactly as L2's A fragments need (relu in-place, zero cvt).
// L2 = mma.m16n8k16 fp32 accum. Weights baked as lane-indexed fragment
// tables in smem; center folded into L1 bias column.

#define N_BLKS 16           // 16 x 4 iters = 64
#define HIDDEN 128
#define SDF_EPS 1e-4f
#define EPS_HIT 5e-5f
#define EPS_MISS 2e-4f

typedef unsigned int u32;

__device__ __forceinline__ float sqap(float x) {
    float r; asm("sqrt.approx.f32 %0,%1;" : "=f"(r) : "f"(x)); return r;
}
__device__ __forceinline__ float rcpa(float x) {
    float r; asm("rcp.approx.f32 %0,%1;" : "=f"(r) : "f"(x)); return r;
}
__device__ __forceinline__ float sgm(float x) {
    return rcpa(1.0f + __expf(-x));
}
// {hi, lo} -> f16x2 (first PTX source is the HIGH half)
__device__ __forceinline__ u32 cvt2(float hi, float lo) {
    u32 r; asm("cvt.rn.f16x2.f32 %0,%1,%2;" : "=r"(r) : "f"(hi), "f"(lo)); return r;
}
__device__ __forceinline__ u32 hmax0(u32 a) {   // relu on f16x2
    u32 r; asm("max.f16x2 %0,%1,%2;" : "=r"(r) : "r"(a), "r"(0u)); return r;
}
// L1: m16n8k8, f16 in / F16 accum. D = {d0,d1} f16x2 regs:
//   d0 = (row lane/4,   cols 2m,2m+1), d1 = (row lane/4+8, cols 2m,2m+1)
__device__ __forceinline__ void mma1688h(u32& d0, u32& d1, u32 a0, u32 a1, u32 b) {
    asm("mma.sync.aligned.m16n8k8.row.col.f16.f16.f16.f16 "
        "{%0,%1},{%2,%3},{%4},{%5,%6};"
        : "=r"(d0), "=r"(d1)
        : "r"(a0), "r"(a1), "r"(b), "r"(0u), "r"(0u));
}
__device__ __forceinline__ void mma16816(float& c0, float& c1, float& c2, float& c3,
                                         u32 a0, u32 a1, u32 a2, u32 a3,
                                         u32 b0, u32 b1) {
    asm("mma.sync.aligned.m16n8k16.row.col.f32.f16.f16.f32 "
        "{%0,%1,%2,%3},{%4,%5,%6,%7},{%8,%9},{%0,%1,%2,%3};"
        : "+f"(c0), "+f"(c1), "+f"(c2), "+f"(c3)
        : "r"(a0), "r"(a1), "r"(a2), "r"(a3), "r"(b0), "r"(b1));
}

__global__ void __launch_bounds__(256)
sphere_trace_kernel(const float* __restrict__ origins,
                    const float* __restrict__ directions,
                    const float* __restrict__ center,
                    const float* __restrict__ radius,
                    const float* __restrict__ W1,
                    const float* __restrict__ b1,
                    const float* __restrict__ W2,
                    const float* __restrict__ b2,
                    float* __restrict__ out,
                    int n_quads)
{
    __shared__ float4 sP4[1024];       // per-ray {qx,qy,qz,sdf}, warp-local use
    __shared__ u32  B1T[512];          // L1 B-frags: [kt][ntile][lane]
    __shared__ uint2 B2T[256];         // L2 B-frags: [kt][lane] -> (b0,b1)

    int t = threadIdx.x;
    float cx = center[0], cy = center[1], cz = center[2];

    // ---- Bake W1 (+bias column, center folded) into m16n8k8 B fragments ----
    // j = 16*kt + 8*nt + lane/4; k-pair = 2*(lane%4).
    // k=0..2 -> W1 row k, k=3 -> b1' = b1 + W1.c, k>=4 -> 0.
    for (int e = t; e < 512; e += 256) {
        int kt = e >> 6, nt = (e >> 5) & 1, ln = e & 31;
        int mm = ln & 3, j = 16 * kt + 8 * nt + (ln >> 2);
        float v[2];
        #pragma unroll
        for (int h = 0; h < 2; ++h) {
            int k = 2 * mm + h;
            float val = 0.f;
            if (k == 0) val = W1[j];
            else if (k == 1) val = W1[HIDDEN + j];
            else if (k == 2) val = W1[2 * HIDDEN + j];
            else if (k == 3) val = b1[j] + W1[j] * cx + W1[HIDDEN + j] * cy
                                   + W1[2 * HIDDEN + j] * cz;
            v[h] = val;
        }
        B1T[e] = cvt2(v[1], v[0]);
    }
    // ---- Bake W2 into m16n8k16 B fragments: j0 = 16*kt + 2*(lane%4), n = lane/4 ----
    for (int e = t; e < 256; e += 256) {
        int kt = e >> 5, ln = e & 31;
        int mm = ln & 3, n = ln >> 2;
        int j0 = 16 * kt + 2 * mm;
        float g0 = (n < 3) ? W2[3 * j0 + n]       : 0.f;
        float g1 = (n < 3) ? W2[3 * (j0 + 1) + n] : 0.f;
        float g8 = (n < 3) ? W2[3 * (j0 + 8) + n] : 0.f;
        float g9 = (n < 3) ? W2[3 * (j0 + 9) + n] : 0.f;
        B2T[e] = make_uint2(cvt2(g1, g0), cvt2(g9, g8));
    }
    __syncthreads();

    if (blockIdx.x * blockDim.x >= (unsigned)n_quads) return;   // uniform guard
    int i = blockIdx.x * blockDim.x + t;   // quad: rays 4i..4i+3

    float rad = radius[0];

    const float4* og = (const float4*)origins;
    const float4* dg = (const float4*)directions;
    float4 A = og[3 * i], B = og[3 * i + 1], C = og[3 * i + 2];
    float4 DA = dg[3 * i], DB = dg[3 * i + 1], DC = dg[3 * i + 2];

    // ---- Scalar trace on centered coords ----
    float qx[4], qy[4], qz[4], vx[4], vy[4], vz[4], s[4], pv[4];
    qx[0] = A.x - cx; qy[0] = A.y - cy; qz[0] = A.z - cz;
    qx[1] = A.w - cx; qy[1] = B.x - cy; qz[1] = B.y - cz;
    qx[2] = B.z - cx; qy[2] = B.w - cy; qz[2] = C.x - cz;
    qx[3] = C.y - cx; qy[3] = C.z - cy; qz[3] = C.w - cz;
    vx[0] = DA.x; vy[0] = DA.y; vz[0] = DA.z;
    vx[1] = DA.w; vy[1] = DB.x; vz[1] = DB.y;
    vx[2] = DB.z; vy[2] = DB.w; vz[2] = DC.x;
    vx[3] = DC.y; vy[3] = DC.z; vz[3] = DC.w;
    #pragma unroll
    for (int r = 0; r < 4; ++r) { s[r] = 0.f; pv[r] = 1e30f; }

    #pragma unroll 1
    for (int blk = 0; blk < N_BLKS; ++blk) {
        #pragma unroll
        for (int u = 0; u < 4; ++u) {
            #pragma unroll
            for (int r = 0; r < 4; ++r) {
                float n2 = fmaf(qx[r], qx[r], fmaf(qy[r], qy[r], qz[r] * qz[r]));
                float sr = sqap(n2) - rad;
                s[r] = sr;
                qx[r] = fmaf(sr, vx[r], qx[r]);
                qy[r] = fmaf(sr, vy[r], qy[r]);
                qz[r] = fmaf(sr, vz[r], qz[r]);
            }
        }
        // Done = converged hit (mask guaranteed 1) or past-perigee miss
        // (mask guaranteed 0). Exit when all 4 rays of this thread are done.
        bool all_done = true;
        #pragma unroll
        for (int r = 0; r < 4; ++r) {
            bool d = (s[r] < EPS_HIT) | ((s[r] > pv[r]) & (s[r] > EPS_MISS));
            all_done &= d;
            pv[r] = s[r];
        }
        if (all_done) break;
    }

    // ---- Stage this thread's 4 rays: {q, sdf} (warp-local consumption) ----
    #pragma unroll
    for (int r = 0; r < 4; ++r)
        sP4[4 * t + r] = make_float4(qx[r], qy[r], qz[r], s[r]);
    __syncwarp();

    // ---- MLP on tensor cores: warp handles its 128 rays = 8 tiles of 16 ----
    int lane = t & 31;
    int mm = lane & 3;
    int ch0 = 2 * mm, ch1 = ch0 + 1;
    float i0 = (ch0 < 3) ? b2[ch0] : 0.f;
    float i1 = (ch1 < 3) ? b2[ch1] : 0.f;
    int wbase = (t >> 5) * 128;
    int grayB = blockIdx.x * 1024;

    #pragma unroll 1
    for (int tile = 0; tile < 8; ++tile) {
        int rA = wbase + tile * 16 + (lane >> 2);
        int rB = rA + 8;
        float4 PA = sP4[rA];
        float4 PB = sP4[rB];

        // L1 A-fragment (constant across ktiles): K = [qx,qy,qz,1,0,0,0,0]
        u32 a0 = 0, a1 = 0;
        if (mm == 0)      { a0 = cvt2(PA.y, PA.x); a1 = cvt2(PB.y, PB.x); }
        else if (mm == 1) { a0 = cvt2(1.0f, PA.z); a1 = cvt2(1.0f, PB.z); }

        float c0 = i0, c1 = i1, c2 = i0, c3 = i1;

        #pragma unroll
        for (int kt = 0; kt < 8; ++kt) {
            u32 b1a = B1T[kt * 64 + lane];
            u32 b1b = B1T[kt * 64 + 32 + lane];
            u32 da0, da1, db0, db1;
            mma1688h(da0, da1, a0, a1, b1a);   // hid 16kt+0..7,  f16 D
            mma1688h(db0, db1, a0, a1, b1b);   // hid 16kt+8..15, f16 D
            u32 h0 = hmax0(da0);   // (rayA, k0 k1)
            u32 h1 = hmax0(da1);   // (rayB, k0 k1)
            u32 h2 = hmax0(db0);   // (rayA, k8 k9)
            u32 h3 = hmax0(db1);   // (rayB, k8 k9)
            uint2 b2f = B2T[kt * 32 + lane];
            mma16816(c0, c1, c2, c3, h0, h1, h2, h3, b2f.x, b2f.y);
        }

        // Epilogue: sigmoid + mask-select (kills inf/NaN miss rays), store.
        bool mA = PA.w < SDF_EPS;
        bool mB = PB.w < SDF_EPS;
        int gA = grayB + rA, gB = grayB + rB;
        if (ch0 < 3) {
            out[3 * gA + ch0] = mA ? sgm(c0) : 0.f;
            out[3 * gB + ch0] = mB ? sgm(c2) : 0.f;
        }
        if (ch1 < 3) {
            out[3 * gA + ch1] = mA ? sgm(c1) : 0.f;
            out[3 * gB + ch1] = mB ? sgm(c3) : 0.f;
        }
    }
}

extern "C" void kernel_launch(void* const* d_in, const int* in_sizes, int n_in,
                              void* d_out, int out_size) {
    const float* origins    = (const float*)d_in[0];
    const float* directions = (const float*)d_in[1];
    const float* center     = (const float*)d_in[2];
    const float* radius     = (const float*)d_in[3];
    const float* W1         = (const float*)d_in[4];
    const float* b1         = (const float*)d_in[5];
    const float* W2         = (const float*)d_in[6];
    const float* b2         = (const float*)d_in[7];
    float* out = (float*)d_out;

    int n_rays = in_sizes[0] / 3;
    int n_quads = n_rays / 4;
    int block = 256;
    int grid = (n_quads + block - 1) / block;
    sphere_trace_kernel<<<grid, block>>>(origins, directions, center, radius,
                                         W1, b1, W2, b2, out, n_quads);
}

// round 12
// speedup vs baseline: 1.7609x; 1.0010x over previous
#include <cuda_runtime.h>
#include <cuda_fp16.h>

// SphereTracingRenderer: fused 64-iter sphere trace + 3->128->3 MLP, masked.
// Trace: scalar fp32, 4 rays/thread, early exit (monotone SDF).
// MLP: tensor cores; L1 = 2x mma.m16n8k8 f16-accum (D == L2 A-frag layout),
// L2 = mma.m16n8k16 fp32-accum with DUAL accumulator chains (even/odd ktiles)
// to double ILP on the serial accumulation path. Block=128 for finer wave
// granularity; epilogue staged via smem -> coalesced float4 stores.

#define N_BLKS 16           // 16 x 4 iters = 64
#define HIDDEN 128
#define SDF_EPS 1e-4f
#define EPS_HIT 5e-5f
#define EPS_MISS 2e-4f
#define BLOCK 128
#define RAYS_PER_BLOCK (BLOCK * 4)   // 512

typedef unsigned int u32;

__device__ __forceinline__ float sqap(float x) {
    float r; asm("sqrt.approx.f32 %0,%1;" : "=f"(r) : "f"(x)); return r;
}
__device__ __forceinline__ float rcpa(float x) {
    float r; asm("rcp.approx.f32 %0,%1;" : "=f"(r) : "f"(x)); return r;
}
__device__ __forceinline__ float sgm(float x) {
    return rcpa(1.0f + __expf(-x));
}
// {hi, lo} -> f16x2 (first PTX source is the HIGH half)
__device__ __forceinline__ u32 cvt2(float hi, float lo) {
    u32 r; asm("cvt.rn.f16x2.f32 %0,%1,%2;" : "=r"(r) : "f"(hi), "f"(lo)); return r;
}
__device__ __forceinline__ u32 hmax0(u32 a) {   // relu on f16x2
    u32 r; asm("max.f16x2 %0,%1,%2;" : "=r"(r) : "r"(a), "r"(0u)); return r;
}
// L1: m16n8k8, f16 in / f16 accum. D = {d0,d1} f16x2 regs.
__device__ __forceinline__ void mma1688h(u32& d0, u32& d1, u32 a0, u32 a1, u32 b) {
    asm("mma.sync.aligned.m16n8k8.row.col.f16.f16.f16.f16 "
        "{%0,%1},{%2,%3},{%4},{%5,%6};"
        : "=r"(d0), "=r"(d1)
        : "r"(a0), "r"(a1), "r"(b), "r"(0u), "r"(0u));
}
__device__ __forceinline__ void mma16816(float& c0, float& c1, float& c2, float& c3,
                                         u32 a0, u32 a1, u32 a2, u32 a3,
                                         u32 b0, u32 b1) {
    asm("mma.sync.aligned.m16n8k16.row.col.f32.f16.f16.f32 "
        "{%0,%1,%2,%3},{%4,%5,%6,%7},{%8,%9},{%0,%1,%2,%3};"
        : "+f"(c0), "+f"(c1), "+f"(c2), "+f"(c3)
        : "r"(a0), "r"(a1), "r"(a2), "r"(a3), "r"(b0), "r"(b1));
}

__global__ void __launch_bounds__(BLOCK)
sphere_trace_kernel(const float* __restrict__ origins,
                    const float* __restrict__ directions,
                    const float* __restrict__ center,
                    const float* __restrict__ radius,
                    const float* __restrict__ W1,
                    const float* __restrict__ b1,
                    const float* __restrict__ W2,
                    const float* __restrict__ b2,
                    float* __restrict__ out,
                    int n_quads)
{
    __shared__ float4 sP4[RAYS_PER_BLOCK];        // {qx,qy,qz,sdf} per ray
    __shared__ float  sOut[RAYS_PER_BLOCK * 3];   // epilogue staging
    __shared__ u32   B1T[512];                    // L1 B-frags [kt][ntile][lane]
    __shared__ uint2 B2T[256];                    // L2 B-frags [kt][lane]

    int t = threadIdx.x;
    float cx = center[0], cy = center[1], cz = center[2];

    // ---- Bake W1 (+bias column, center folded) into m16n8k8 B fragments ----
    for (int e = t; e < 512; e += BLOCK) {
        int kt = e >> 6, nt = (e >> 5) & 1, ln = e & 31;
        int mm = ln & 3, j = 16 * kt + 8 * nt + (ln >> 2);
        float v[2];
        #pragma unroll
        for (int h = 0; h < 2; ++h) {
            int k = 2 * mm + h;
            float val = 0.f;
            if (k == 0) val = W1[j];
            else if (k == 1) val = W1[HIDDEN + j];
            else if (k == 2) val = W1[2 * HIDDEN + j];
            else if (k == 3) val = b1[j] + W1[j] * cx + W1[HIDDEN + j] * cy
                                   + W1[2 * HIDDEN + j] * cz;
            v[h] = val;
        }
        B1T[e] = cvt2(v[1], v[0]);
    }
    // ---- Bake W2 into m16n8k16 B fragments ----
    for (int e = t; e < 256; e += BLOCK) {
        int kt = e >> 5, ln = e & 31;
        int mm = ln & 3, n = ln >> 2;
        int j0 = 16 * kt + 2 * mm;
        float g0 = (n < 3) ? W2[3 * j0 + n]       : 0.f;
        float g1 = (n < 3) ? W2[3 * (j0 + 1) + n] : 0.f;
        float g8 = (n < 3) ? W2[3 * (j0 + 8) + n] : 0.f;
        float g9 = (n < 3) ? W2[3 * (j0 + 9) + n] : 0.f;
        B2T[e] = make_uint2(cvt2(g1, g0), cvt2(g9, g8));
    }
    __syncthreads();

    if (blockIdx.x * BLOCK >= (unsigned)n_quads) return;   // uniform guard
    int i = blockIdx.x * BLOCK + t;   // quad: rays 4i..4i+3

    float rad = radius[0];

    const float4* og = (const float4*)origins;
    const float4* dg = (const float4*)directions;
    float4 A = og[3 * i], B = og[3 * i + 1], C = og[3 * i + 2];
    float4 DA = dg[3 * i], DB = dg[3 * i + 1], DC = dg[3 * i + 2];

    // ---- Scalar trace on centered coords ----
    float qx[4], qy[4], qz[4], vx[4], vy[4], vz[4], s[4], pv[4];
    qx[0] = A.x - cx; qy[0] = A.y - cy; qz[0] = A.z - cz;
    qx[1] = A.w - cx; qy[1] = B.x - cy; qz[1] = B.y - cz;
    qx[2] = B.z - cx; qy[2] = B.w - cy; qz[2] = C.x - cz;
    qx[3] = C.y - cx; qy[3] = C.z - cy; qz[3] = C.w - cz;
    vx[0] = DA.x; vy[0] = DA.y; vz[0] = DA.z;
    vx[1] = DA.w; vy[1] = DB.x; vz[1] = DB.y;
    vx[2] = DB.z; vy[2] = DB.w; vz[2] = DC.x;
    vx[3] = DC.y; vy[3] = DC.z; vz[3] = DC.w;
    #pragma unroll
    for (int r = 0; r < 4; ++r) { s[r] = 0.f; pv[r] = 1e30f; }

    #pragma unroll 1
    for (int blk = 0; blk < N_BLKS; ++blk) {
        #pragma unroll
        for (int u = 0; u < 4; ++u) {
            #pragma unroll
            for (int r = 0; r < 4; ++r) {
                float n2 = fmaf(qx[r], qx[r], fmaf(qy[r], qy[r], qz[r] * qz[r]));
                float sr = sqap(n2) - rad;
                s[r] = sr;
                qx[r] = fmaf(sr, vx[r], qx[r]);
                qy[r] = fmaf(sr, vy[r], qy[r]);
                qz[r] = fmaf(sr, vz[r], qz[r]);
            }
        }
        // Done = converged hit (mask guaranteed 1) or past-perigee miss
        // (mask guaranteed 0). Exit when all 4 rays of this thread are done.
        bool all_done = true;
        #pragma unroll
        for (int r = 0; r < 4; ++r) {
            bool d = (s[r] < EPS_HIT) | ((s[r] > pv[r]) & (s[r] > EPS_MISS));
            all_done &= d;
            pv[r] = s[r];
        }
        if (all_done) break;
    }

    // ---- Stage rays (warp-local consumption) ----
    #pragma unroll
    for (int r = 0; r < 4; ++r)
        sP4[4 * t + r] = make_float4(qx[r], qy[r], qz[r], s[r]);
    __syncwarp();

    // ---- MLP on tensor cores: warp handles its 128 rays = 8 tiles of 16 ----
    int lane = t & 31;
    int mm = lane & 3;
    int ch0 = 2 * mm, ch1 = ch0 + 1;
    float i0 = (ch0 < 3) ? b2[ch0] : 0.f;
    float i1 = (ch1 < 3) ? b2[ch1] : 0.f;
    int wbase = (t >> 5) * 128;

    #pragma unroll 1
    for (int tile = 0; tile < 8; ++tile) {
        int rA = wbase + tile * 16 + (lane >> 2);
        int rB = rA + 8;
        float4 PA = sP4[rA];
        float4 PB = sP4[rB];

        // L1 A-fragment: K = [qx,qy,qz,1,0,0,0,0]
        u32 a0 = 0, a1 = 0;
        if (mm == 0)      { a0 = cvt2(PA.y, PA.x); a1 = cvt2(PB.y, PB.x); }
        else if (mm == 1) { a0 = cvt2(1.0f, PA.z); a1 = cvt2(1.0f, PB.z); }

        // Dual accumulator chains: even ktiles -> c*, odd ktiles -> e*.
        float c0 = i0, c1 = i1, c2 = i0, c3 = i1;
        float e0 = 0.f, e1 = 0.f, e2 = 0.f, e3 = 0.f;

        #pragma unroll
        for (int kt = 0; kt < 8; kt += 2) {
            {
                u32 b1a = B1T[kt * 64 + lane];
                u32 b1b = B1T[kt * 64 + 32 + lane];
                u32 da0, da1, db0, db1;
                mma1688h(da0, da1, a0, a1, b1a);
                mma1688h(db0, db1, a0, a1, b1b);
                uint2 b2f = B2T[kt * 32 + lane];
                mma16816(c0, c1, c2, c3, hmax0(da0), hmax0(da1),
                         hmax0(db0), hmax0(db1), b2f.x, b2f.y);
            }
            {
                int ko = kt + 1;
                u32 b1a = B1T[ko * 64 + lane];
                u32 b1b = B1T[ko * 64 + 32 + lane];
                u32 da0, da1, db0, db1;
                mma1688h(da0, da1, a0, a1, b1a);
                mma1688h(db0, db1, a0, a1, b1b);
                uint2 b2f = B2T[ko * 32 + lane];
                mma16816(e0, e1, e2, e3, hmax0(da0), hmax0(da1),
                         hmax0(db0), hmax0(db1), b2f.x, b2f.y);
            }
        }
        c0 += e0; c1 += e1; c2 += e2; c3 += e3;

        // Epilogue: sigmoid + mask-select, stage to smem (coalesced STG later).
        bool mA = PA.w < SDF_EPS;
        bool mB = PB.w < SDF_EPS;
        if (ch0 < 3) {
            sOut[3 * rA + ch0] = mA ? sgm(c0) : 0.f;
            sOut[3 * rB + ch0] = mB ? sgm(c2) : 0.f;
        }
        if (ch1 < 3) {
            sOut[3 * rA + ch1] = mA ? sgm(c1) : 0.f;
            sOut[3 * rB + ch1] = mB ? sgm(c3) : 0.f;
        }
    }
    __syncwarp();

    // ---- Coalesced store: thread t's quad -> out[12i .. 12i+12) ----
    float4* o4 = (float4*)out;
    const float4* sO4 = (const float4*)sOut;
    #pragma unroll
    for (int k = 0; k < 3; ++k)
        o4[3 * i + k] = sO4[3 * t + k];
}

extern "C" void kernel_launch(void* const* d_in, const int* in_sizes, int n_in,
                              void* d_out, int out_size) {
    const float* origins    = (const float*)d_in[0];
    const float* directions = (const float*)d_in[1];
    const float* center     = (const float*)d_in[2];
    const float* radius     = (const float*)d_in[3];
    const float* W1         = (const float*)d_in[4];
    const float* b1         = (const float*)d_in[5];
    const float* W2         = (const float*)d_in[6];
    const float* b2         = (const float*)d_in[7];
    float* out = (float*)d_out;

    int n_rays = in_sizes[0] / 3;
    int n_quads = n_rays / 4;
    int grid = (n_quads + BLOCK - 1) / BLOCK;
    sphere_trace_kernel<<<grid, BLOCK>>>(origins, directions, center, radius,
                                         W1, b1, W2, b2, out, n_quads);
}

// round 13
// speedup vs baseline: 1.7754x; 1.0082x over previous
#include <cuda_runtime.h>
#include <cuda_fp16.h>

// SphereTracingRenderer: fused 64-iter sphere trace + 3->128->3 MLP, masked.
// Trace: 1-D reparametrization — updates are always along d, so iterate the
// scalar t with n2 = t^2 + 2*beta*t + gamma (2 fma-pipe ops + MUFU per iter
// instead of 9): t_{n+1} = t_n + (sqrt(n2)-R). 4 rays/thread, early exit
// (monotone SDF). Final points rebuilt from a reload of o,d (L2-hot).
// MLP: tensor cores; L1 = 2x mma.m16n8k8 f16-accum (D == L2 A-frag layout),
// L2 = mma.m16n8k16 fp32-accum, dual accumulator chains. Epilogue staged
// via smem -> coalesced float4 stores.

#define N_BLKS 16           // 16 x 4 iters = 64
#define HIDDEN 128
#define SDF_EPS 1e-4f
#define EPS_HIT 5e-5f
#define EPS_MISS 2e-4f
#define BLOCK 128
#define RAYS_PER_BLOCK (BLOCK * 4)   // 512

typedef unsigned int u32;

__device__ __forceinline__ float sqap(float x) {
    float r; asm("sqrt.approx.f32 %0,%1;" : "=f"(r) : "f"(x)); return r;
}
__device__ __forceinline__ float rcpa(float x) {
    float r; asm("rcp.approx.f32 %0,%1;" : "=f"(r) : "f"(x)); return r;
}
__device__ __forceinline__ float sgm(float x) {
    return rcpa(1.0f + __expf(-x));
}
// {hi, lo} -> f16x2 (first PTX source is the HIGH half)
__device__ __forceinline__ u32 cvt2(float hi, float lo) {
    u32 r; asm("cvt.rn.f16x2.f32 %0,%1,%2;" : "=r"(r) : "f"(hi), "f"(lo)); return r;
}
__device__ __forceinline__ u32 hmax0(u32 a) {   // relu on f16x2
    u32 r; asm("max.f16x2 %0,%1,%2;" : "=r"(r) : "r"(a), "r"(0u)); return r;
}
// L1: m16n8k8, f16 in / f16 accum. D = {d0,d1} f16x2 regs.
__device__ __forceinline__ void mma1688h(u32& d0, u32& d1, u32 a0, u32 a1, u32 b) {
    asm("mma.sync.aligned.m16n8k8.row.col.f16.f16.f16.f16 "
        "{%0,%1},{%2,%3},{%4},{%5,%6};"
        : "=r"(d0), "=r"(d1)
        : "r"(a0), "r"(a1), "r"(b), "r"(0u), "r"(0u));
}
__device__ __forceinline__ void mma16816(float& c0, float& c1, float& c2, float& c3,
                                         u32 a0, u32 a1, u32 a2, u32 a3,
                                         u32 b0, u32 b1) {
    asm("mma.sync.aligned.m16n8k16.row.col.f32.f16.f16.f32 "
        "{%0,%1,%2,%3},{%4,%5,%6,%7},{%8,%9},{%0,%1,%2,%3};"
        : "+f"(c0), "+f"(c1), "+f"(c2), "+f"(c3)
        : "r"(a0), "r"(a1), "r"(a2), "r"(a3), "r"(b0), "r"(b1));
}

__global__ void __launch_bounds__(BLOCK)
sphere_trace_kernel(const float* __restrict__ origins,
                    const float* __restrict__ directions,
                    const float* __restrict__ center,
                    const float* __restrict__ radius,
                    const float* __restrict__ W1,
                    const float* __restrict__ b1,
                    const float* __restrict__ W2,
                    const float* __restrict__ b2,
                    float* __restrict__ out,
                    int n_quads)
{
    __shared__ float4 sP4[RAYS_PER_BLOCK];        // {qx,qy,qz,sdf} per ray
    __shared__ float  sOut[RAYS_PER_BLOCK * 3];   // epilogue staging
    __shared__ u32   B1T[512];                    // L1 B-frags [kt][ntile][lane]
    __shared__ uint2 B2T[256];                    // L2 B-frags [kt][lane]

    int t = threadIdx.x;
    float cx = center[0], cy = center[1], cz = center[2];

    // ---- Bake W1 (+bias column, center folded) into m16n8k8 B fragments ----
    for (int e = t; e < 512; e += BLOCK) {
        int kt = e >> 6, nt = (e >> 5) & 1, ln = e & 31;
        int mm = ln & 3, j = 16 * kt + 8 * nt + (ln >> 2);
        float v[2];
        #pragma unroll
        for (int h = 0; h < 2; ++h) {
            int k = 2 * mm + h;
            float val = 0.f;
            if (k == 0) val = W1[j];
            else if (k == 1) val = W1[HIDDEN + j];
            else if (k == 2) val = W1[2 * HIDDEN + j];
            else if (k == 3) val = b1[j] + W1[j] * cx + W1[HIDDEN + j] * cy
                                   + W1[2 * HIDDEN + j] * cz;
            v[h] = val;
        }
        B1T[e] = cvt2(v[1], v[0]);
    }
    // ---- Bake W2 into m16n8k16 B fragments ----
    for (int e = t; e < 256; e += BLOCK) {
        int kt = e >> 5, ln = e & 31;
        int mm = ln & 3, n = ln >> 2;
        int j0 = 16 * kt + 2 * mm;
        float g0 = (n < 3) ? W2[3 * j0 + n]       : 0.f;
        float g1 = (n < 3) ? W2[3 * (j0 + 1) + n] : 0.f;
        float g8 = (n < 3) ? W2[3 * (j0 + 8) + n] : 0.f;
        float g9 = (n < 3) ? W2[3 * (j0 + 9) + n] : 0.f;
        B2T[e] = make_uint2(cvt2(g1, g0), cvt2(g9, g8));
    }
    __syncthreads();

    if (blockIdx.x * BLOCK >= (unsigned)n_quads) return;   // uniform guard
    int i = blockIdx.x * BLOCK + t;   // quad: rays 4i..4i+3

    float rad = radius[0];

    const float4* og = (const float4*)origins;
    const float4* dg = (const float4*)directions;

    // ---- 1-D trace setup: per ray, gamma = |o-c|^2, tb2 = 2 d.(o-c) ----
    float ga[4], tb2[4], tt[4], s[4], pv[4];
    {
        float4 A = og[3 * i], B = og[3 * i + 1], C = og[3 * i + 2];
        float4 DA = dg[3 * i], DB = dg[3 * i + 1], DC = dg[3 * i + 2];
        float ox[4] = {A.x - cx, A.w - cx, B.z - cx, C.y - cx};
        float oy[4] = {A.y - cy, B.x - cy, B.w - cy, C.z - cy};
        float oz[4] = {A.z - cz, B.y - cz, C.x - cz, C.w - cz};
        float dx[4] = {DA.x, DA.w, DB.z, DC.y};
        float dy[4] = {DA.y, DB.x, DB.w, DC.z};
        float dz[4] = {DA.z, DB.y, DC.x, DC.w};
        #pragma unroll
        for (int r = 0; r < 4; ++r) {
            ga[r]  = fmaf(ox[r], ox[r], fmaf(oy[r], oy[r], oz[r] * oz[r]));
            float b = fmaf(ox[r], dx[r], fmaf(oy[r], dy[r], oz[r] * dz[r]));
            tb2[r] = b + b;
            tt[r] = 0.f;
            s[r] = 0.f;
            pv[r] = 1e30f;
        }
    }

    #pragma unroll 1
    for (int blk = 0; blk < N_BLKS; ++blk) {
        #pragma unroll
        for (int u = 0; u < 4; ++u) {
            #pragma unroll
            for (int r = 0; r < 4; ++r) {
                float n2 = fmaf(tt[r], tt[r] + tb2[r], ga[r]);
                float sr = sqap(n2) - rad;
                s[r] = sr;
                tt[r] += sr;
            }
        }
        // Done = converged hit (mask guaranteed 1) or past-perigee miss
        // (mask guaranteed 0). Exit when all 4 rays of this thread are done.
        bool all_done = true;
        #pragma unroll
        for (int r = 0; r < 4; ++r) {
            bool d = (s[r] < EPS_HIT) | ((s[r] > pv[r]) & (s[r] > EPS_MISS));
            all_done &= d;
            pv[r] = s[r];
        }
        if (all_done) break;
    }

    // ---- Rebuild final centered points q = (o-c) + t*d (reload o,d) ----
    {
        float4 A = og[3 * i], B = og[3 * i + 1], C = og[3 * i + 2];
        float4 DA = dg[3 * i], DB = dg[3 * i + 1], DC = dg[3 * i + 2];
        sP4[4 * t + 0] = make_float4(fmaf(tt[0], DA.x, A.x - cx),
                                     fmaf(tt[0], DA.y, A.y - cy),
                                     fmaf(tt[0], DA.z, A.z - cz), s[0]);
        sP4[4 * t + 1] = make_float4(fmaf(tt[1], DA.w, A.w - cx),
                                     fmaf(tt[1], DB.x, B.x - cy),
                                     fmaf(tt[1], DB.y, B.y - cz), s[1]);
        sP4[4 * t + 2] = make_float4(fmaf(tt[2], DB.z, B.z - cx),
                                     fmaf(tt[2], DB.w, B.w - cy),
                                     fmaf(tt[2], DC.x, C.x - cz), s[2]);
        sP4[4 * t + 3] = make_float4(fmaf(tt[3], DC.y, C.y - cx),
                                     fmaf(tt[3], DC.z, C.z - cy),
                                     fmaf(tt[3], DC.w, C.w - cz), s[3]);
    }
    __syncwarp();

    // ---- MLP on tensor cores: warp handles its 128 rays = 8 tiles of 16 ----
    int lane = t & 31;
    int mm = lane & 3;
    int ch0 = 2 * mm, ch1 = ch0 + 1;
    float i0 = (ch0 < 3) ? b2[ch0] : 0.f;
    float i1 = (ch1 < 3) ? b2[ch1] : 0.f;
    int wbase = (t >> 5) * 128;

    #pragma unroll 1
    for (int tile = 0; tile < 8; ++tile) {
        int rA = wbase + tile * 16 + (lane >> 2);
        int rB = rA + 8;
        float4 PA = sP4[rA];
        float4 PB = sP4[rB];

        // L1 A-fragment: K = [qx,qy,qz,1,0,0,0,0]
        u32 a0 = 0, a1 = 0;
        if (mm == 0)      { a0 = cvt2(PA.y, PA.x); a1 = cvt2(PB.y, PB.x); }
        else if (mm == 1) { a0 = cvt2(1.0f, PA.z); a1 = cvt2(1.0f, PB.z); }

        // Dual accumulator chains: even ktiles -> c*, odd ktiles -> e*.
        float c0 = i0, c1 = i1, c2 = i0, c3 = i1;
        float e0 = 0.f, e1 = 0.f, e2 = 0.f, e3 = 0.f;

        #pragma unroll
        for (int kt = 0; kt < 8; kt += 2) {
            {
                u32 b1a = B1T[kt * 64 + lane];
                u32 b1b = B1T[kt * 64 + 32 + lane];
                u32 da0, da1, db0, db1;
                mma1688h(da0, da1, a0, a1, b1a);
                mma1688h(db0, db1, a0, a1, b1b);
                uint2 b2f = B2T[kt * 32 + lane];
                mma16816(c0, c1, c2, c3, hmax0(da0), hmax0(da1),
                         hmax0(db0), hmax0(db1), b2f.x, b2f.y);
            }
            {
                int ko = kt + 1;
                u32 b1a = B1T[ko * 64 + lane];
                u32 b1b = B1T[ko * 64 + 32 + lane];
                u32 da0, da1, db0, db1;
                mma1688h(da0, da1, a0, a1, b1a);
                mma1688h(db0, db1, a0, a1, b1b);
                uint2 b2f = B2T[ko * 32 + lane];
                mma16816(e0, e1, e2, e3, hmax0(da0), hmax0(da1),
                         hmax0(db0), hmax0(db1), b2f.x, b2f.y);
            }
        }
        c0 += e0; c1 += e1; c2 += e2; c3 += e3;

        // Epilogue: sigmoid + mask-select, stage to smem (coalesced STG later).
        bool mA = PA.w < SDF_EPS;
        bool mB = PB.w < SDF_EPS;
        if (ch0 < 3) {
            sOut[3 * rA + ch0] = mA ? sgm(c0) : 0.f;
            sOut[3 * rB + ch0] = mB ? sgm(c2) : 0.f;
        }
        if (ch1 < 3) {
            sOut[3 * rA + ch1] = mA ? sgm(c1) : 0.f;
            sOut[3 * rB + ch1] = mB ? sgm(c3) : 0.f;
        }
    }
    __syncwarp();

    // ---- Coalesced store: thread t's quad -> out[12i .. 12i+12) ----
    float4* o4 = (float4*)out;
    const float4* sO4 = (const float4*)sOut;
    #pragma unroll
    for (int k = 0; k < 3; ++k)
        o4[3 * i + k] = sO4[3 * t + k];
}

extern "C" void kernel_launch(void* const* d_in, const int* in_sizes, int n_in,
                              void* d_out, int out_size) {
    const float* origins    = (const float*)d_in[0];
    const float* directions = (const float*)d_in[1];
    const float* center     = (const float*)d_in[2];
    const float* radius     = (const float*)d_in[3];
    const float* W1         = (const float*)d_in[4];
    const float* b1         = (const float*)d_in[5];
    const float* W2         = (const float*)d_in[6];
    const float* b2         = (const float*)d_in[7];
    float* out = (float*)d_out;

    int n_rays = in_sizes[0] / 3;
    int n_quads = n_rays / 4;
    int grid = (n_quads + BLOCK - 1) / BLOCK;
    sphere_trace_kernel<<<grid, BLOCK>>>(origins, directions, center, radius,
                                         W1, b1, W2, b2, out, n_quads);
}

// round 14
// speedup vs baseline: 1.8553x; 1.0450x over previous
#include <cuda_runtime.h>
#include <cuda_fp16.h>

// SphereTracingRenderer: fused 64-iter sphere trace + 3->128->3 MLP, masked.
// Trace: 1-D reparametrization (t-only iteration: fma + MUFU per step),
// 2 rays/thread, early exit (monotone SDF). Points rebuilt from o,d reload.
// MLP: tensor cores; L1 = 2x mma.m16n8k8 f16-accum (D == L2 A-frag layout),
// L2 = mma.m16n8k16 fp32-accum, dual accumulator chains.
// Block=256, 2 rays/thread: MLP per-thread register demand is invariant to
// rays/thread, so this config maximizes resident warps (~5 CTAs/SM).

#define N_BLKS 16           // 16 x 4 iters = 64
#define HIDDEN 128
#define SDF_EPS 1e-4f
#define EPS_HIT 5e-5f
#define EPS_MISS 2e-4f
#define BLOCK 256
#define RAYS_PER_BLOCK (BLOCK * 2)   // 512

typedef unsigned int u32;

__device__ __forceinline__ float sqap(float x) {
    float r; asm("sqrt.approx.f32 %0,%1;" : "=f"(r) : "f"(x)); return r;
}
__device__ __forceinline__ float rcpa(float x) {
    float r; asm("rcp.approx.f32 %0,%1;" : "=f"(r) : "f"(x)); return r;
}
__device__ __forceinline__ float sgm(float x) {
    return rcpa(1.0f + __expf(-x));
}
// {hi, lo} -> f16x2 (first PTX source is the HIGH half)
__device__ __forceinline__ u32 cvt2(float hi, float lo) {
    u32 r; asm("cvt.rn.f16x2.f32 %0,%1,%2;" : "=r"(r) : "f"(hi), "f"(lo)); return r;
}
__device__ __forceinline__ u32 hmax0(u32 a) {   // relu on f16x2
    u32 r; asm("max.f16x2 %0,%1,%2;" : "=r"(r) : "r"(a), "r"(0u)); return r;
}
// L1: m16n8k8, f16 in / f16 accum. D = {d0,d1} f16x2 regs.
__device__ __forceinline__ void mma1688h(u32& d0, u32& d1, u32 a0, u32 a1, u32 b) {
    asm("mma.sync.aligned.m16n8k8.row.col.f16.f16.f16.f16 "
        "{%0,%1},{%2,%3},{%4},{%5,%6};"
        : "=r"(d0), "=r"(d1)
        : "r"(a0), "r"(a1), "r"(b), "r"(0u), "r"(0u));
}
__device__ __forceinline__ void mma16816(float& c0, float& c1, float& c2, float& c3,
                                         u32 a0, u32 a1, u32 a2, u32 a3,
                                         u32 b0, u32 b1) {
    asm("mma.sync.aligned.m16n8k16.row.col.f32.f16.f16.f32 "
        "{%0,%1,%2,%3},{%4,%5,%6,%7},{%8,%9},{%0,%1,%2,%3};"
        : "+f"(c0), "+f"(c1), "+f"(c2), "+f"(c3)
        : "r"(a0), "r"(a1), "r"(a2), "r"(a3), "r"(b0), "r"(b1));
}

__global__ void __launch_bounds__(BLOCK)
sphere_trace_kernel(const float* __restrict__ origins,
                    const float* __restrict__ directions,
                    const float* __restrict__ center,
                    const float* __restrict__ radius,
                    const float* __restrict__ W1,
                    const float* __restrict__ b1,
                    const float* __restrict__ W2,
                    const float* __restrict__ b2,
                    float* __restrict__ out,
                    int n_pairs)
{
    __shared__ float4 sP4[RAYS_PER_BLOCK];        // {qx,qy,qz,sdf} per ray
    __shared__ float  sOut[RAYS_PER_BLOCK * 3];   // epilogue staging
    __shared__ u32   B1T[512];                    // L1 B-frags [kt][ntile][lane]
    __shared__ uint2 B2T[256];                    // L2 B-frags [kt][lane]

    int t = threadIdx.x;
    float cx = center[0], cy = center[1], cz = center[2];

    // ---- Bake W1 (+bias column, center folded) into m16n8k8 B fragments ----
    for (int e = t; e < 512; e += BLOCK) {
        int kt = e >> 6, nt = (e >> 5) & 1, ln = e & 31;
        int mm = ln & 3, j = 16 * kt + 8 * nt + (ln >> 2);
        float v[2];
        #pragma unroll
        for (int h = 0; h < 2; ++h) {
            int k = 2 * mm + h;
            float val = 0.f;
            if (k == 0) val = W1[j];
            else if (k == 1) val = W1[HIDDEN + j];
            else if (k == 2) val = W1[2 * HIDDEN + j];
            else if (k == 3) val = b1[j] + W1[j] * cx + W1[HIDDEN + j] * cy
                                   + W1[2 * HIDDEN + j] * cz;
            v[h] = val;
        }
        B1T[e] = cvt2(v[1], v[0]);
    }
    // ---- Bake W2 into m16n8k16 B fragments ----
    for (int e = t; e < 256; e += BLOCK) {
        int kt = e >> 5, ln = e & 31;
        int mm = ln & 3, n = ln >> 2;
        int j0 = 16 * kt + 2 * mm;
        float g0 = (n < 3) ? W2[3 * j0 + n]       : 0.f;
        float g1 = (n < 3) ? W2[3 * (j0 + 1) + n] : 0.f;
        float g8 = (n < 3) ? W2[3 * (j0 + 8) + n] : 0.f;
        float g9 = (n < 3) ? W2[3 * (j0 + 9) + n] : 0.f;
        B2T[e] = make_uint2(cvt2(g1, g0), cvt2(g9, g8));
    }
    __syncthreads();

    if (blockIdx.x * BLOCK >= (unsigned)n_pairs) return;   // uniform guard
    int i = blockIdx.x * BLOCK + t;   // pair index: rays 2i, 2i+1

    float rad = radius[0];

    const float2* og2 = (const float2*)origins;
    const float2* dg2 = (const float2*)directions;

    // ---- 1-D trace setup: per ray, gamma = |o-c|^2, tb2 = 2 d.(o-c) ----
    // ray0 = (a.x,a.y,b.x); ray1 = (b.y,c.x,c.y)
    float ga[2], tb2[2], tt[2], s[2], pv[2];
    {
        float2 oa = og2[3 * i], ob = og2[3 * i + 1], oc = og2[3 * i + 2];
        float2 da = dg2[3 * i], db = dg2[3 * i + 1], dc = dg2[3 * i + 2];
        float ox[2] = {oa.x - cx, ob.y - cx};
        float oy[2] = {oa.y - cy, oc.x - cy};
        float oz[2] = {ob.x - cz, oc.y - cz};
        float dx[2] = {da.x, db.y};
        float dy[2] = {da.y, dc.x};
        float dz[2] = {db.x, dc.y};
        #pragma unroll
        for (int r = 0; r < 2; ++r) {
            ga[r]  = fmaf(ox[r], ox[r], fmaf(oy[r], oy[r], oz[r] * oz[r]));
            float b = fmaf(ox[r], dx[r], fmaf(oy[r], dy[r], oz[r] * dz[r]));
            tb2[r] = b + b;
            tt[r] = 0.f;
            s[r] = 0.f;
            pv[r] = 1e30f;
        }
    }

    #pragma unroll 1
    for (int blk = 0; blk < N_BLKS; ++blk) {
        #pragma unroll
        for (int u = 0; u < 4; ++u) {
            #pragma unroll
            for (int r = 0; r < 2; ++r) {
                float n2 = fmaf(tt[r], tt[r] + tb2[r], ga[r]);
                float sr = sqap(n2) - rad;
                s[r] = sr;
                tt[r] += sr;
            }
        }
        // Done = converged hit (mask guaranteed 1) or past-perigee miss
        // (mask guaranteed 0). Exit when both rays of this thread are done.
        bool d0 = (s[0] < EPS_HIT) | ((s[0] > pv[0]) & (s[0] > EPS_MISS));
        bool d1 = (s[1] < EPS_HIT) | ((s[1] > pv[1]) & (s[1] > EPS_MISS));
        pv[0] = s[0]; pv[1] = s[1];
        if (d0 & d1) break;
    }

    // ---- Rebuild final centered points q = (o-c) + t*d (reload o,d) ----
    {
        float2 oa = og2[3 * i], ob = og2[3 * i + 1], oc = og2[3 * i + 2];
        float2 da = dg2[3 * i], db = dg2[3 * i + 1], dc = dg2[3 * i + 2];
        sP4[2 * t + 0] = make_float4(fmaf(tt[0], da.x, oa.x - cx),
                                     fmaf(tt[0], da.y, oa.y - cy),
                                     fmaf(tt[0], db.x, ob.x - cz), s[0]);
        sP4[2 * t + 1] = make_float4(fmaf(tt[1], db.y, ob.y - cx),
                                     fmaf(tt[1], dc.x, oc.x - cy),
                                     fmaf(tt[1], dc.y, oc.y - cz), s[1]);
    }
    __syncwarp();

    // ---- MLP on tensor cores: warp handles its 64 rays = 4 tiles of 16 ----
    int lane = t & 31;
    int mm = lane & 3;
    int ch0 = 2 * mm, ch1 = ch0 + 1;
    float i0 = (ch0 < 3) ? b2[ch0] : 0.f;
    float i1 = (ch1 < 3) ? b2[ch1] : 0.f;
    int wbase = (t >> 5) * 64;

    #pragma unroll 1
    for (int tile = 0; tile < 4; ++tile) {
        int rA = wbase + tile * 16 + (lane >> 2);
        int rB = rA + 8;
        float4 PA = sP4[rA];
        float4 PB = sP4[rB];

        // L1 A-fragment: K = [qx,qy,qz,1,0,0,0,0]
        u32 a0 = 0, a1 = 0;
        if (mm == 0)      { a0 = cvt2(PA.y, PA.x); a1 = cvt2(PB.y, PB.x); }
        else if (mm == 1) { a0 = cvt2(1.0f, PA.z); a1 = cvt2(1.0f, PB.z); }

        // Dual accumulator chains: even ktiles -> c*, odd ktiles -> e*.
        float c0 = i0, c1 = i1, c2 = i0, c3 = i1;
        float e0 = 0.f, e1 = 0.f, e2 = 0.f, e3 = 0.f;

        #pragma unroll
        for (int kt = 0; kt < 8; kt += 2) {
            {
                u32 b1a = B1T[kt * 64 + lane];
                u32 b1b = B1T[kt * 64 + 32 + lane];
                u32 da0, da1, db0, db1;
                mma1688h(da0, da1, a0, a1, b1a);
                mma1688h(db0, db1, a0, a1, b1b);
                uint2 b2f = B2T[kt * 32 + lane];
                mma16816(c0, c1, c2, c3, hmax0(da0), hmax0(da1),
                         hmax0(db0), hmax0(db1), b2f.x, b2f.y);
            }
            {
                int ko = kt + 1;
                u32 b1a = B1T[ko * 64 + lane];
                u32 b1b = B1T[ko * 64 + 32 + lane];
                u32 da0, da1, db0, db1;
                mma1688h(da0, da1, a0, a1, b1a);
                mma1688h(db0, db1, a0, a1, b1b);
                uint2 b2f = B2T[ko * 32 + lane];
                mma16816(e0, e1, e2, e3, hmax0(da0), hmax0(da1),
                         hmax0(db0), hmax0(db1), b2f.x, b2f.y);
            }
        }
        c0 += e0; c1 += e1; c2 += e2; c3 += e3;

        // Epilogue: sigmoid + mask-select, stage to smem.
        bool mA = PA.w < SDF_EPS;
        bool mB = PB.w < SDF_EPS;
        if (ch0 < 3) {
            sOut[3 * rA + ch0] = mA ? sgm(c0) : 0.f;
            sOut[3 * rB + ch0] = mB ? sgm(c2) : 0.f;
        }
        if (ch1 < 3) {
            sOut[3 * rA + ch1] = mA ? sgm(c1) : 0.f;
            sOut[3 * rB + ch1] = mB ? sgm(c3) : 0.f;
        }
    }
    __syncwarp();

    // ---- Store own pair (warp-local staging): floats 6i .. 6i+6 ----
    float2* o2 = (float2*)out;
    const float2* sO2 = (const float2*)sOut;
    #pragma unroll
    for (int k = 0; k < 3; ++k)
        o2[3 * i + k] = sO2[3 * t + k];
}

extern "C" void kernel_launch(void* const* d_in, const int* in_sizes, int n_in,
                              void* d_out, int out_size) {
    const float* origins    = (const float*)d_in[0];
    const float* directions = (const float*)d_in[1];
    const float* center     = (const float*)d_in[2];
    const float* radius     = (const float*)d_in[3];
    const float* W1         = (const float*)d_in[4];
    const float* b1         = (const float*)d_in[5];
    const float* W2         = (const float*)d_in[6];
    const float* b2         = (const float*)d_in[7];
    float* out = (float*)d_out;

    int n_rays = in_sizes[0] / 3;
    int n_pairs = n_rays / 2;
    int grid = (n_pairs + BLOCK - 1) / BLOCK;
    sphere_trace_kernel<<<grid, BLOCK>>>(origins, directions, center, radius,
                                         W1, b1, W2, b2, out, n_pairs);
}